// round 1
// baseline (speedup 1.0000x reference)
#include <cuda_runtime.h>
#include <cstdint>
#include <math.h>

// Problem constants
constexpr int Bc  = 2;
constexpr int Lc  = 2048;
constexpr int Dc  = 1024;
constexpr int NHc = 16;
constexpr int HSc = 64;      // D / NH
constexpr int TDc = 3 * Dc;  // 3072
constexpr int Mrows = Bc * Lc; // 4096

// Scratch (static device globals — allocation is forbidden)
__device__ float g_qkv[(size_t)Bc * Lc * TDc]; // [B*L, 3D]
__device__ float g_y  [(size_t)Bc * Lc * Dc];  // [B*L, D]

// ---------------------------------------------------------------------------
// Generic fp32 GEMM + bias: C[M,N] = A[M,K] @ B[K,N] + bias[N]
// 128x128 tile, BK=16, 256 threads, 8x8 per thread.
// ---------------------------------------------------------------------------
__global__ __launch_bounds__(256) void sgemm_bias(
    const float* __restrict__ A, const float* __restrict__ Bm,
    const float* __restrict__ bias, float* __restrict__ C,
    int M, int N, int K)
{
    constexpr int BM = 128, BN = 128, BK = 16;
    __shared__ float As[BK][BM + 4];
    __shared__ float Bs[BK][BN];

    const int tid = threadIdx.x;
    const int tx = tid & 15;   // 0..15
    const int ty = tid >> 4;   // 0..15
    const int i0 = blockIdx.y * BM;
    const int j0 = blockIdx.x * BN;

    float acc[8][8];
#pragma unroll
    for (int r = 0; r < 8; r++)
#pragma unroll
        for (int c = 0; c < 8; c++) acc[r][c] = 0.f;

    for (int k0 = 0; k0 < K; k0 += BK) {
        // A tile: 128 rows x 16 k  (512 float4, 2 per thread), store transposed
#pragma unroll
        for (int t = 0; t < 2; t++) {
            int idx = tid + t * 256;          // 0..511
            int row = idx >> 2;               // 0..127
            int kc  = (idx & 3) * 4;          // 0,4,8,12
            float4 v = *reinterpret_cast<const float4*>(
                A + (size_t)(i0 + row) * K + k0 + kc);
            As[kc + 0][row] = v.x;
            As[kc + 1][row] = v.y;
            As[kc + 2][row] = v.z;
            As[kc + 3][row] = v.w;
        }
        // B tile: 16 x 128 (512 float4, 2 per thread)
#pragma unroll
        for (int t = 0; t < 2; t++) {
            int idx = tid + t * 256;
            int kk = idx >> 5;                // 0..15
            int jc = (idx & 31) * 4;          // 0..124
            *reinterpret_cast<float4*>(&Bs[kk][jc]) =
                *reinterpret_cast<const float4*>(
                    Bm + (size_t)(k0 + kk) * N + j0 + jc);
        }
        __syncthreads();

#pragma unroll
        for (int k = 0; k < BK; k++) {
            float a[8], b[8];
#pragma unroll
            for (int r = 0; r < 8; r++) a[r] = As[k][ty + 16 * r];
#pragma unroll
            for (int c = 0; c < 8; c++) b[c] = Bs[k][tx + 16 * c];
#pragma unroll
            for (int r = 0; r < 8; r++)
#pragma unroll
                for (int c = 0; c < 8; c++)
                    acc[r][c] = fmaf(a[r], b[c], acc[r][c]);
        }
        __syncthreads();
    }

    float bv[8];
#pragma unroll
    for (int c = 0; c < 8; c++) bv[c] = bias[j0 + tx + 16 * c];
#pragma unroll
    for (int r = 0; r < 8; r++) {
        size_t rowoff = (size_t)(i0 + ty + 16 * r) * N + j0;
#pragma unroll
        for (int c = 0; c < 8; c++)
            C[rowoff + tx + 16 * c] = acc[r][c] + bv[c];
    }
}

// ---------------------------------------------------------------------------
// Flash attention with relative-position term.
//   s[i,j] = (q_i . k_j + q_i . Er[L-1-(i-j)]) * 1/sqrt(HS),  j <= i
// 64(q) x 64(k) tiles, HS=64. 256 threads, thread (tx,ty) owns
// rows i = ty+16r (r=0..3), cols j = tx+16c (c=0..3) -> all smem reads
// are broadcast or stride-65 conflict-free.
// ---------------------------------------------------------------------------
constexpr int ST = 65; // smem row stride (floats), odd -> conflict-free
constexpr int ATTN_SMEM_FLOATS = 4 * 64 * ST + 128 * ST; // Q,K,V,P + Er band
constexpr int ATTN_SMEM_BYTES  = ATTN_SMEM_FLOATS * 4;   // 99840

__global__ __launch_bounds__(256) void attn_relpos_kernel(
    const float* __restrict__ qkv, const float* __restrict__ Er,
    float* __restrict__ y)
{
    extern __shared__ float sm[];
    float* Qs = sm;                 // [64][ST]
    float* Ks = Qs + 64 * ST;       // [64][ST]
    float* Vs = Ks + 64 * ST;       // [64][ST]
    float* Ps = Vs + 64 * ST;       // [64][ST]
    float* Es = Ps + 64 * ST;       // [128][ST]

    const int qt = blockIdx.x;            // query tile (0..31)
    const int bh = blockIdx.y;            // b*NH + h
    const int b  = bh >> 4;
    const int h  = bh & 15;
    const int i0 = qt * 64;

    const int tid = threadIdx.x;
    const int tx = tid & 15;
    const int ty = tid >> 4;

    // Load Q tile
    const float* qbase = qkv + ((size_t)(b * Lc + i0)) * TDc + h * HSc;
    for (int idx = tid; idx < 64 * 64; idx += 256) {
        int r = idx >> 6, c = idx & 63;
        Qs[r * ST + c] = qbase[(size_t)r * TDc + c];
    }

    float o[4][4];
    float mrow[4], lrow[4];
#pragma unroll
    for (int r = 0; r < 4; r++) {
        mrow[r] = -INFINITY;
        lrow[r] = 0.f;
#pragma unroll
        for (int c = 0; c < 4; c++) o[r][c] = 0.f;
    }

    const int eb = 63 + tx - ty;  // band index base for this thread

    for (int kt = 0; kt <= qt; ++kt) {
        const int j0 = kt * 64;
        __syncthreads(); // previous PV done (and Qs ready on first iter)

        const float* kbase = qkv + ((size_t)(b * Lc + j0)) * TDc + Dc + h * HSc;
        const float* vbase = kbase + Dc;
        for (int idx = tid; idx < 64 * 64; idx += 256) {
            int r = idx >> 6, c = idx & 63;
            Ks[r * ST + c] = kbase[(size_t)r * TDc + c];
            Vs[r * ST + c] = vbase[(size_t)r * TDc + c];
        }
        // Er band: m = mbase + e, e in [0,127] (127 used); clamp masked rows
        const int mbase = (Lc - 64) - i0 + j0;  // >= 0 always
        for (int idx = tid; idx < 128 * 64; idx += 256) {
            int e = idx >> 6, c = idx & 63;
            int m = mbase + e;
            m = m < (Lc - 1) ? m : (Lc - 1);
            Es[e * ST + c] = Er[(size_t)m * HSc + c];
        }
        __syncthreads();

        // ---- S = Q K^T + Q Er^T (banded) ----
        float s[4][4];
#pragma unroll
        for (int r = 0; r < 4; r++)
#pragma unroll
            for (int c = 0; c < 4; c++) s[r][c] = 0.f;

#pragma unroll 4
        for (int d = 0; d < 64; ++d) {
            float qv[4], kv[4], ev[7];
#pragma unroll
            for (int r = 0; r < 4; r++) qv[r] = Qs[(ty + 16 * r) * ST + d];
#pragma unroll
            for (int c = 0; c < 4; c++) kv[c] = Ks[(tx + 16 * c) * ST + d];
#pragma unroll
            for (int k = 0; k < 7; k++) ev[k] = Es[(eb + 16 * (k - 3)) * ST + d];
#pragma unroll
            for (int r = 0; r < 4; r++)
#pragma unroll
                for (int c = 0; c < 4; c++) {
                    s[r][c] = fmaf(qv[r], kv[c], s[r][c]);
                    s[r][c] = fmaf(qv[r], ev[c - r + 3], s[r][c]);
                }
        }

        // ---- scale + causal mask ----
        const float scale = 0.125f; // 1/sqrt(64)
#pragma unroll
        for (int r = 0; r < 4; r++)
#pragma unroll
            for (int c = 0; c < 4; c++) {
                float v = s[r][c] * scale;
                if (j0 + tx + 16 * c > i0 + ty + 16 * r) v = -INFINITY;
                s[r][c] = v;
            }

        // ---- online softmax (row groups = 16 lanes sharing ty) ----
        float mnew[4], alpha[4];
#pragma unroll
        for (int r = 0; r < 4; r++) {
            float rm = s[r][0];
#pragma unroll
            for (int c = 1; c < 4; c++) rm = fmaxf(rm, s[r][c]);
#pragma unroll
            for (int off = 1; off < 16; off <<= 1)
                rm = fmaxf(rm, __shfl_xor_sync(0xFFFFFFFFu, rm, off));
            mnew[r]  = fmaxf(mrow[r], rm);
            alpha[r] = __expf(mrow[r] - mnew[r]);
        }
#pragma unroll
        for (int r = 0; r < 4; r++) {
            float rs = 0.f;
#pragma unroll
            for (int c = 0; c < 4; c++) {
                float p = __expf(s[r][c] - mnew[r]);
                s[r][c] = p;
                rs += p;
            }
#pragma unroll
            for (int off = 1; off < 16; off <<= 1)
                rs += __shfl_xor_sync(0xFFFFFFFFu, rs, off);
            lrow[r] = lrow[r] * alpha[r] + rs;
            mrow[r] = mnew[r];
        }

        // stash P, rescale O
#pragma unroll
        for (int r = 0; r < 4; r++)
#pragma unroll
            for (int c = 0; c < 4; c++) {
                Ps[(ty + 16 * r) * ST + tx + 16 * c] = s[r][c];
                o[r][c] *= alpha[r];
            }
        __syncthreads();

        // ---- O += P V  (same row ownership; cols d = tx+16c) ----
#pragma unroll 4
        for (int j = 0; j < 64; ++j) {
            float pv[4], vv[4];
#pragma unroll
            for (int r = 0; r < 4; r++) pv[r] = Ps[(ty + 16 * r) * ST + j];
#pragma unroll
            for (int c = 0; c < 4; c++) vv[c] = Vs[j * ST + tx + 16 * c];
#pragma unroll
            for (int r = 0; r < 4; r++)
#pragma unroll
                for (int c = 0; c < 4; c++)
                    o[r][c] = fmaf(pv[r], vv[c], o[r][c]);
        }
    }

    // ---- epilogue: y[b, i, h*HS + d] = O / l ----
#pragma unroll
    for (int r = 0; r < 4; r++) {
        float inv = 1.f / lrow[r];
        int i = i0 + ty + 16 * r;
        size_t rowoff = ((size_t)(b * Lc + i)) * Dc + h * HSc;
#pragma unroll
        for (int c = 0; c < 4; c++)
            y[rowoff + tx + 16 * c] = o[r][c] * inv;
    }
}

// ---------------------------------------------------------------------------
extern "C" void kernel_launch(void* const* d_in, const int* in_sizes, int n_in,
                              void* d_out, int out_size)
{
    const float* x     = (const float*)d_in[0]; // [B,L,D]
    const float* Wqkv  = (const float*)d_in[1]; // [D,3D]
    const float* bqkv  = (const float*)d_in[2]; // [3D]
    const float* Wproj = (const float*)d_in[3]; // [D,D]
    const float* bproj = (const float*)d_in[4]; // [D]
    const float* Er    = (const float*)d_in[5]; // [L,HS]
    float* out = (float*)d_out;

    float *qkvp, *yp;
    cudaGetSymbolAddress((void**)&qkvp, g_qkv);
    cudaGetSymbolAddress((void**)&yp, g_y);

    cudaFuncSetAttribute(attn_relpos_kernel,
                         cudaFuncAttributeMaxDynamicSharedMemorySize,
                         ATTN_SMEM_BYTES);

    dim3 blk(256);
    // 1) qkv = x @ Wqkv + bqkv        [4096, 3072]
    sgemm_bias<<<dim3(TDc / 128, Mrows / 128), blk>>>(
        x, Wqkv, bqkv, qkvp, Mrows, TDc, Dc);
    // 2) flash attention with rel-pos -> y [4096, 1024]
    attn_relpos_kernel<<<dim3(Lc / 64, Bc * NHc), blk, ATTN_SMEM_BYTES>>>(
        qkvp, Er, yp);
    // 3) out = y @ Wproj + bproj      [4096, 1024]
    sgemm_bias<<<dim3(Dc / 128, Mrows / 128), blk>>>(
        yp, Wproj, bproj, out, Mrows, Dc, Dc);
}

// round 4
// speedup vs baseline: 1.1528x; 1.1528x over previous
#include <cuda_runtime.h>
#include <cstdint>
#include <math.h>

// Problem constants
constexpr int Bc  = 2;
constexpr int Lc  = 2048;
constexpr int Dc  = 1024;
constexpr int NHc = 16;
constexpr int HSc = 64;
constexpr int TDc = 3 * Dc;       // 3072
constexpr int Mrows = Bc * Lc;    // 4096

// ---------------- static scratch (no allocation allowed) ----------------
__device__ float g_xh[(size_t)Mrows * Dc];
__device__ float g_xl[(size_t)Mrows * Dc];
__device__ float g_wqkvt_h[(size_t)TDc * Dc];   // Wqkv^T [3072,1024] hi
__device__ float g_wqkvt_l[(size_t)TDc * Dc];
__device__ float g_wprojt_h[(size_t)Dc * Dc];   // Wproj^T [1024,1024] hi
__device__ float g_wprojt_l[(size_t)Dc * Dc];
__device__ float g_qkv[(size_t)Mrows * TDc];
__device__ float g_y[(size_t)Mrows * Dc];
__device__ float g_yh[(size_t)Mrows * Dc];
__device__ float g_yl[(size_t)Mrows * Dc];

// ---------------- helpers ----------------
__device__ __forceinline__ uint32_t smem_u32(const void* p) {
    uint32_t a;
    asm("{ .reg .u64 t; cvta.to.shared.u64 t, %1; cvt.u32.u64 %0, t; }"
        : "=r"(a) : "l"(p));
    return a;
}
__device__ __forceinline__ void cp16(uint32_t saddr, const void* g) {
    asm volatile("cp.async.cg.shared.global [%0], [%1], 16;" :: "r"(saddr), "l"(g));
}
__device__ __forceinline__ void cp_commit() { asm volatile("cp.async.commit_group;"); }
template <int N> __device__ __forceinline__ void cp_wait() {
    asm volatile("cp.async.wait_group %0;" :: "n"(N));
}
__device__ __forceinline__ float tf32_hi(float a) {
    return __uint_as_float(__float_as_uint(a) & 0xFFFFE000u);
}
// D += A(tf32) * B(tf32), m16n8k8 row.col
__device__ __forceinline__ void mma1688(float* d, const uint32_t* a, const uint32_t* b) {
    asm volatile(
        "mma.sync.aligned.m16n8k8.row.col.f32.tf32.tf32.f32 "
        "{%0,%1,%2,%3}, {%4,%5,%6,%7}, {%8,%9}, {%0,%1,%2,%3};"
        : "+f"(d[0]), "+f"(d[1]), "+f"(d[2]), "+f"(d[3])
        : "r"(a[0]), "r"(a[1]), "r"(a[2]), "r"(a[3]), "r"(b[0]), "r"(b[1]));
}

// ---------------- split / transpose pre-passes ----------------
__global__ __launch_bounds__(256) void split_tf32(
    const float* __restrict__ in, float* __restrict__ hi, float* __restrict__ lo, int n4)
{
    int i = blockIdx.x * 256 + threadIdx.x;
    if (i >= n4) return;
    float4 v = reinterpret_cast<const float4*>(in)[i];
    float4 h, l;
    h.x = tf32_hi(v.x); l.x = v.x - h.x;
    h.y = tf32_hi(v.y); l.y = v.y - h.y;
    h.z = tf32_hi(v.z); l.z = v.z - h.z;
    h.w = tf32_hi(v.w); l.w = v.w - h.w;
    reinterpret_cast<float4*>(hi)[i] = h;
    reinterpret_cast<float4*>(lo)[i] = l;
}

// W [K,N] -> Th, Tl [N,K]
__global__ __launch_bounds__(256) void transpose_split(
    const float* __restrict__ W, float* __restrict__ Th, float* __restrict__ Tl,
    int K, int N)
{
    __shared__ float t[32][33];
    int n0 = blockIdx.x * 32, k0 = blockIdx.y * 32;
    int tx = threadIdx.x, ty = threadIdx.y;   // 32 x 8
#pragma unroll
    for (int r = 0; r < 4; r++)
        t[ty + 8 * r][tx] = W[(size_t)(k0 + ty + 8 * r) * N + n0 + tx];
    __syncthreads();
#pragma unroll
    for (int r = 0; r < 4; r++) {
        float v = t[tx][ty + 8 * r];
        float h = tf32_hi(v);
        size_t o = (size_t)(n0 + ty + 8 * r) * K + k0 + tx;
        Th[o] = h;
        Tl[o] = v - h;
    }
}

// ---------------- mma.sync tf32 split GEMM ----------------
// C[M,N] = A[M,K] @ Bt[N,K]^T + bias (fp32-accurate, 3-product tf32 split)
// CTA 128x128, BK=32, 8 warps (warp tile 64x32), double-buffered cp.async.
constexpr int SSTR   = 36;                 // smem row stride in floats (36%32=4 -> conflict-free frags)
constexpr int TILE_F = 128 * SSTR;         // floats per 128x32 tile buffer
constexpr int TILE_B = TILE_F * 4;         // 18432 bytes
constexpr uint32_t GSMEM = 2u * 4u * TILE_B; // 2 stages * {Ah,Al,Bh,Bl} = 147456

__device__ __forceinline__ void g_load_chunk(
    uint32_t sbase, int stage,
    const float* Ah, const float* Al, const float* Bh, const float* Bl,
    int i0, int j0, int K, int kc, int tid)
{
    const int kofs = kc * 32;
    const float* srcs[4] = { Ah, Al, Bh, Bl };
#pragma unroll
    for (int tile = 0; tile < 4; tile++) {
        const float* src = srcs[tile];
        const int rbase = (tile < 2) ? i0 : j0;
        uint32_t tb = sbase + (uint32_t)(stage * 4 + tile) * TILE_B;
#pragma unroll
        for (int it = 0; it < 4; it++) {
            int idx = tid + it * 256;   // 0..1023
            int row = idx >> 3;         // 0..127
            int c4  = idx & 7;          // 0..7
            cp16(tb + (uint32_t)(row * (SSTR * 4) + c4 * 16),
                 src + (size_t)(rbase + row) * K + kofs + c4 * 4);
        }
    }
}

__global__ __launch_bounds__(256) void gemm_mma_split(
    const float* __restrict__ Ah, const float* __restrict__ Al,
    const float* __restrict__ Bh, const float* __restrict__ Bl,
    const float* __restrict__ bias, float* __restrict__ C,
    int M, int N, int K)
{
    extern __shared__ float sm[];
    const uint32_t sbase = smem_u32(sm);
    const int tid  = threadIdx.x;
    const int lane = tid & 31;
    const int wid  = tid >> 5;
    const int wm   = wid & 1;      // warp row (0..1) -> 64 rows
    const int wn   = wid >> 1;     // warp col (0..3) -> 32 cols
    const int g    = lane >> 2;    // group id 0..7
    const int t4   = lane & 3;     // thread in group 0..3
    const int i0 = blockIdx.y * 128, j0 = blockIdx.x * 128;
    const int nk = K / 32;

    float acc[16][4];
#pragma unroll
    for (int i = 0; i < 16; i++)
#pragma unroll
        for (int j = 0; j < 4; j++) acc[i][j] = 0.f;

    g_load_chunk(sbase, 0, Ah, Al, Bh, Bl, i0, j0, K, 0, tid); cp_commit();
    g_load_chunk(sbase, 1, Ah, Al, Bh, Bl, i0, j0, K, 1, tid); cp_commit();

    for (int kc = 0; kc < nk; kc++) {
        const int s = kc & 1;
        if (kc + 2 < nk) cp_wait<1>(); else cp_wait<0>();
        __syncthreads();

        const uint32_t* sAh = (const uint32_t*)(sm + (s * 4 + 0) * TILE_F);
        const uint32_t* sAl = (const uint32_t*)(sm + (s * 4 + 1) * TILE_F);
        const uint32_t* sBh = (const uint32_t*)(sm + (s * 4 + 2) * TILE_F);
        const uint32_t* sBl = (const uint32_t*)(sm + (s * 4 + 3) * TILE_F);

#pragma unroll
        for (int ks = 0; ks < 4; ks++) {
            const int kcol = ks * 8 + t4;
            uint32_t ah[4][4], al[4][4], bh[4][2], bl[4][2];
#pragma unroll
            for (int mt = 0; mt < 4; mt++) {
                int base = (wm * 64 + mt * 16 + g) * SSTR + kcol;
                ah[mt][0] = sAh[base];
                ah[mt][1] = sAh[base + 8 * SSTR];
                ah[mt][2] = sAh[base + 4];
                ah[mt][3] = sAh[base + 8 * SSTR + 4];
                al[mt][0] = sAl[base];
                al[mt][1] = sAl[base + 8 * SSTR];
                al[mt][2] = sAl[base + 4];
                al[mt][3] = sAl[base + 8 * SSTR + 4];
            }
#pragma unroll
            for (int nt = 0; nt < 4; nt++) {
                int base = (wn * 32 + nt * 8 + g) * SSTR + kcol;
                bh[nt][0] = sBh[base];
                bh[nt][1] = sBh[base + 4];
                bl[nt][0] = sBl[base];
                bl[nt][1] = sBl[base + 4];
            }
#pragma unroll
            for (int mt = 0; mt < 4; mt++)
#pragma unroll
                for (int nt = 0; nt < 4; nt++) {
                    float* d = acc[mt * 4 + nt];
                    mma1688(d, ah[mt], bh[nt]);   // hi*hi
                    mma1688(d, ah[mt], bl[nt]);   // hi*lo
                    mma1688(d, al[mt], bh[nt]);   // lo*hi
                }
        }
        __syncthreads();
        if (kc + 2 < nk) {
            g_load_chunk(sbase, s, Ah, Al, Bh, Bl, i0, j0, K, kc + 2, tid);
            cp_commit();
        }
    }

    // epilogue
#pragma unroll
    for (int mt = 0; mt < 4; mt++) {
#pragma unroll
        for (int nt = 0; nt < 4; nt++) {
            const float* d = acc[mt * 4 + nt];
            int row = i0 + wm * 64 + mt * 16 + g;
            int col = j0 + wn * 32 + nt * 8 + 2 * t4;
            float b0 = bias[col], b1 = bias[col + 1];
            float2 v0 = { d[0] + b0, d[1] + b1 };
            float2 v1 = { d[2] + b0, d[3] + b1 };
            *reinterpret_cast<float2*>(C + (size_t)row * N + col) = v0;
            *reinterpret_cast<float2*>(C + (size_t)(row + 8) * N + col) = v1;
        }
    }
}

// ---------------------------------------------------------------------------
// Flash attention with relative-position term (fp32 SIMT, from R1).
// ---------------------------------------------------------------------------
constexpr int ST = 65;
constexpr int ATTN_SMEM_FLOATS = 4 * 64 * ST + 128 * ST;
constexpr int ATTN_SMEM_BYTES  = ATTN_SMEM_FLOATS * 4;

__global__ __launch_bounds__(256) void attn_relpos_kernel(
    const float* __restrict__ qkv, const float* __restrict__ Er,
    float* __restrict__ y)
{
    extern __shared__ float smf[];
    float* Qs = smf;
    float* Ks = Qs + 64 * ST;
    float* Vs = Ks + 64 * ST;
    float* Ps = Vs + 64 * ST;
    float* Es = Ps + 64 * ST;

    const int qt = blockIdx.x;
    const int bh = blockIdx.y;
    const int b  = bh >> 4;
    const int h  = bh & 15;
    const int i0 = qt * 64;

    const int tid = threadIdx.x;
    const int tx = tid & 15;
    const int ty = tid >> 4;

    const float* qbase = qkv + ((size_t)(b * Lc + i0)) * TDc + h * HSc;
    for (int idx = tid; idx < 64 * 64; idx += 256) {
        int r = idx >> 6, c = idx & 63;
        Qs[r * ST + c] = qbase[(size_t)r * TDc + c];
    }

    float o[4][4];
    float mrow[4], lrow[4];
#pragma unroll
    for (int r = 0; r < 4; r++) {
        mrow[r] = -INFINITY;
        lrow[r] = 0.f;
#pragma unroll
        for (int c = 0; c < 4; c++) o[r][c] = 0.f;
    }

    const int eb = 63 + tx - ty;

    for (int kt = 0; kt <= qt; ++kt) {
        const int j0 = kt * 64;
        __syncthreads();

        const float* kbase = qkv + ((size_t)(b * Lc + j0)) * TDc + Dc + h * HSc;
        const float* vbase = kbase + Dc;
        for (int idx = tid; idx < 64 * 64; idx += 256) {
            int r = idx >> 6, c = idx & 63;
            Ks[r * ST + c] = kbase[(size_t)r * TDc + c];
            Vs[r * ST + c] = vbase[(size_t)r * TDc + c];
        }
        const int mbase = (Lc - 64) - i0 + j0;
        for (int idx = tid; idx < 128 * 64; idx += 256) {
            int e = idx >> 6, c = idx & 63;
            int m = mbase + e;
            m = m < (Lc - 1) ? m : (Lc - 1);
            Es[e * ST + c] = Er[(size_t)m * HSc + c];
        }
        __syncthreads();

        float s[4][4];
#pragma unroll
        for (int r = 0; r < 4; r++)
#pragma unroll
            for (int c = 0; c < 4; c++) s[r][c] = 0.f;

#pragma unroll 4
        for (int d = 0; d < 64; ++d) {
            float qv[4], kv[4], ev[7];
#pragma unroll
            for (int r = 0; r < 4; r++) qv[r] = Qs[(ty + 16 * r) * ST + d];
#pragma unroll
            for (int c = 0; c < 4; c++) kv[c] = Ks[(tx + 16 * c) * ST + d];
#pragma unroll
            for (int k = 0; k < 7; k++) ev[k] = Es[(eb + 16 * (k - 3)) * ST + d];
#pragma unroll
            for (int r = 0; r < 4; r++)
#pragma unroll
                for (int c = 0; c < 4; c++) {
                    s[r][c] = fmaf(qv[r], kv[c], s[r][c]);
                    s[r][c] = fmaf(qv[r], ev[c - r + 3], s[r][c]);
                }
        }

        const float scale = 0.125f;
#pragma unroll
        for (int r = 0; r < 4; r++)
#pragma unroll
            for (int c = 0; c < 4; c++) {
                float v = s[r][c] * scale;
                if (j0 + tx + 16 * c > i0 + ty + 16 * r) v = -INFINITY;
                s[r][c] = v;
            }

        float mnew[4], alpha[4];
#pragma unroll
        for (int r = 0; r < 4; r++) {
            float rm = s[r][0];
#pragma unroll
            for (int c = 1; c < 4; c++) rm = fmaxf(rm, s[r][c]);
#pragma unroll
            for (int off = 1; off < 16; off <<= 1)
                rm = fmaxf(rm, __shfl_xor_sync(0xFFFFFFFFu, rm, off));
            mnew[r]  = fmaxf(mrow[r], rm);
            alpha[r] = __expf(mrow[r] - mnew[r]);
        }
#pragma unroll
        for (int r = 0; r < 4; r++) {
            float rs = 0.f;
#pragma unroll
            for (int c = 0; c < 4; c++) {
                float p = __expf(s[r][c] - mnew[r]);
                s[r][c] = p;
                rs += p;
            }
#pragma unroll
            for (int off = 1; off < 16; off <<= 1)
                rs += __shfl_xor_sync(0xFFFFFFFFu, rs, off);
            lrow[r] = lrow[r] * alpha[r] + rs;
            mrow[r] = mnew[r];
        }

#pragma unroll
        for (int r = 0; r < 4; r++)
#pragma unroll
            for (int c = 0; c < 4; c++) {
                Ps[(ty + 16 * r) * ST + tx + 16 * c] = s[r][c];
                o[r][c] *= alpha[r];
            }
        __syncthreads();

#pragma unroll 4
        for (int j = 0; j < 64; ++j) {
            float pv[4], vv[4];
#pragma unroll
            for (int r = 0; r < 4; r++) pv[r] = Ps[(ty + 16 * r) * ST + j];
#pragma unroll
            for (int c = 0; c < 4; c++) vv[c] = Vs[j * ST + tx + 16 * c];
#pragma unroll
            for (int r = 0; r < 4; r++)
#pragma unroll
                for (int c = 0; c < 4; c++)
                    o[r][c] = fmaf(pv[r], vv[c], o[r][c]);
        }
    }

#pragma unroll
    for (int r = 0; r < 4; r++) {
        float inv = 1.f / lrow[r];
        int i = i0 + ty + 16 * r;
        size_t rowoff = ((size_t)(b * Lc + i)) * Dc + h * HSc;
#pragma unroll
        for (int c = 0; c < 4; c++)
            y[rowoff + tx + 16 * c] = o[r][c] * inv;
    }
}

// ---------------------------------------------------------------------------
extern "C" void kernel_launch(void* const* d_in, const int* in_sizes, int n_in,
                              void* d_out, int out_size)
{
    const float* x     = (const float*)d_in[0];
    const float* Wqkv  = (const float*)d_in[1];
    const float* bqkv  = (const float*)d_in[2];
    const float* Wproj = (const float*)d_in[3];
    const float* bproj = (const float*)d_in[4];
    const float* Er    = (const float*)d_in[5];
    float* out = (float*)d_out;

    float *xh, *xl, *wqh, *wql, *wph, *wpl, *qkvp, *yp, *yh, *yl;
    cudaGetSymbolAddress((void**)&xh, g_xh);
    cudaGetSymbolAddress((void**)&xl, g_xl);
    cudaGetSymbolAddress((void**)&wqh, g_wqkvt_h);
    cudaGetSymbolAddress((void**)&wql, g_wqkvt_l);
    cudaGetSymbolAddress((void**)&wph, g_wprojt_h);
    cudaGetSymbolAddress((void**)&wpl, g_wprojt_l);
    cudaGetSymbolAddress((void**)&qkvp, g_qkv);
    cudaGetSymbolAddress((void**)&yp, g_y);
    cudaGetSymbolAddress((void**)&yh, g_yh);
    cudaGetSymbolAddress((void**)&yl, g_yl);

    cudaFuncSetAttribute(gemm_mma_split,
                         cudaFuncAttributeMaxDynamicSharedMemorySize, (int)GSMEM);
    cudaFuncSetAttribute(attn_relpos_kernel,
                         cudaFuncAttributeMaxDynamicSharedMemorySize, ATTN_SMEM_BYTES);

    // split inputs / weights into tf32 hi/lo (weights transposed to [N,K])
    int n4x = Mrows * Dc / 4;
    split_tf32<<<(n4x + 255) / 256, 256>>>(x, xh, xl, n4x);
    transpose_split<<<dim3(TDc / 32, Dc / 32), dim3(32, 8)>>>(Wqkv, wqh, wql, Dc, TDc);
    transpose_split<<<dim3(Dc / 32, Dc / 32), dim3(32, 8)>>>(Wproj, wph, wpl, Dc, Dc);

    // qkv = x @ Wqkv + bqkv
    gemm_mma_split<<<dim3(TDc / 128, Mrows / 128), 256, GSMEM>>>(
        xh, xl, wqh, wql, bqkv, qkvp, Mrows, TDc, Dc);

    // flash attention
    attn_relpos_kernel<<<dim3(Lc / 64, Bc * NHc), 256, ATTN_SMEM_BYTES>>>(
        qkvp, Er, yp);

    // out = y @ Wproj + bproj
    split_tf32<<<(n4x + 255) / 256, 256>>>(yp, yh, yl, n4x);
    gemm_mma_split<<<dim3(Dc / 128, Mrows / 128), 256, GSMEM>>>(
        yh, yl, wph, wpl, bproj, out, Mrows, Dc, Dc);
}

// round 7
// speedup vs baseline: 1.4380x; 1.2473x over previous
#include <cuda_runtime.h>
#include <cstdint>
#include <math.h>

// Problem constants
constexpr int Bc  = 2;
constexpr int Lc  = 2048;
constexpr int Dc  = 1024;
constexpr int NHc = 16;
constexpr int HSc = 64;
constexpr int TDc = 3 * Dc;       // 3072
constexpr int Mrows = Bc * Lc;    // 4096

// ---------------- static scratch (no allocation allowed) ----------------
__device__ float g_xh[(size_t)Mrows * Dc];
__device__ float g_xl[(size_t)Mrows * Dc];
__device__ float g_wqkvt_h[(size_t)TDc * Dc];
__device__ float g_wqkvt_l[(size_t)TDc * Dc];
__device__ float g_wprojt_h[(size_t)Dc * Dc];
__device__ float g_wprojt_l[(size_t)Dc * Dc];
__device__ float g_qkv[(size_t)Mrows * TDc];
__device__ float g_y[(size_t)Mrows * Dc];
__device__ float g_yh[(size_t)Mrows * Dc];
__device__ float g_yl[(size_t)Mrows * Dc];

// ---------------- helpers ----------------
__device__ __forceinline__ uint32_t smem_u32(const void* p) {
    uint32_t a;
    asm("{ .reg .u64 t; cvta.to.shared.u64 t, %1; cvt.u32.u64 %0, t; }"
        : "=r"(a) : "l"(p));
    return a;
}
__device__ __forceinline__ void cp16(uint32_t saddr, const void* g) {
    asm volatile("cp.async.cg.shared.global [%0], [%1], 16;" :: "r"(saddr), "l"(g));
}
__device__ __forceinline__ void cp_commit() { asm volatile("cp.async.commit_group;"); }
template <int N> __device__ __forceinline__ void cp_wait() {
    asm volatile("cp.async.wait_group %0;" :: "n"(N));
}
__device__ __forceinline__ float tf32_hi(float a) {
    return __uint_as_float(__float_as_uint(a) & 0xFFFFE000u);
}
__device__ __forceinline__ void mma1688(float* d, const uint32_t* a, const uint32_t* b) {
    asm volatile(
        "mma.sync.aligned.m16n8k8.row.col.f32.tf32.tf32.f32 "
        "{%0,%1,%2,%3}, {%4,%5,%6,%7}, {%8,%9}, {%0,%1,%2,%3};"
        : "+f"(d[0]), "+f"(d[1]), "+f"(d[2]), "+f"(d[3])
        : "r"(a[0]), "r"(a[1]), "r"(a[2]), "r"(a[3]), "r"(b[0]), "r"(b[1]));
}
__device__ __forceinline__ void mma1688b(float* d, const uint32_t* a,
                                         uint32_t b0, uint32_t b1) {
    asm volatile(
        "mma.sync.aligned.m16n8k8.row.col.f32.tf32.tf32.f32 "
        "{%0,%1,%2,%3}, {%4,%5,%6,%7}, {%8,%9}, {%0,%1,%2,%3};"
        : "+f"(d[0]), "+f"(d[1]), "+f"(d[2]), "+f"(d[3])
        : "r"(a[0]), "r"(a[1]), "r"(a[2]), "r"(a[3]), "r"(b0), "r"(b1));
}
// 3-product tf32 split: d += a*b with a given as hi/lo frags, b split here.
__device__ __forceinline__ void mma3(float* d, const uint32_t* ah, const uint32_t* al,
                                     float b0, float b1) {
    float b0h = tf32_hi(b0), b1h = tf32_hi(b1);
    uint32_t B0h = __float_as_uint(b0h), B1h = __float_as_uint(b1h);
    uint32_t B0l = __float_as_uint(b0 - b0h), B1l = __float_as_uint(b1 - b1h);
    mma1688b(d, ah, B0h, B1h);
    mma1688b(d, ah, B0l, B1l);
    mma1688b(d, al, B0h, B1h);
}

// ---------------- split / transpose pre-passes (validated) ----------------
__global__ __launch_bounds__(256) void split_tf32(
    const float* __restrict__ in, float* __restrict__ hi, float* __restrict__ lo, int n4)
{
    int i = blockIdx.x * 256 + threadIdx.x;
    if (i >= n4) return;
    float4 v = reinterpret_cast<const float4*>(in)[i];
    float4 h, l;
    h.x = tf32_hi(v.x); l.x = v.x - h.x;
    h.y = tf32_hi(v.y); l.y = v.y - h.y;
    h.z = tf32_hi(v.z); l.z = v.z - h.z;
    h.w = tf32_hi(v.w); l.w = v.w - h.w;
    reinterpret_cast<float4*>(hi)[i] = h;
    reinterpret_cast<float4*>(lo)[i] = l;
}

// W [K,N] -> Th, Tl [N,K]
__global__ __launch_bounds__(256) void transpose_split(
    const float* __restrict__ W, float* __restrict__ Th, float* __restrict__ Tl,
    int K, int N)
{
    __shared__ float t[32][33];
    int n0 = blockIdx.x * 32, k0 = blockIdx.y * 32;
    int tx = threadIdx.x, ty = threadIdx.y;
#pragma unroll
    for (int r = 0; r < 4; r++)
        t[ty + 8 * r][tx] = W[(size_t)(k0 + ty + 8 * r) * N + n0 + tx];
    __syncthreads();
#pragma unroll
    for (int r = 0; r < 4; r++) {
        float v = t[tx][ty + 8 * r];
        float h = tf32_hi(v);
        size_t o = (size_t)(n0 + ty + 8 * r) * K + k0 + tx;
        Th[o] = h;
        Tl[o] = v - h;
    }
}

// ---------------- mma.sync tf32 split GEMM (passing since R4) ----------------
constexpr int SSTR   = 36;
constexpr int TILE_F = 128 * SSTR;
constexpr int TILE_B = TILE_F * 4;
constexpr uint32_t GSMEM = 2u * 4u * TILE_B;

__device__ __forceinline__ void g_load_chunk(
    uint32_t sbase, int stage,
    const float* Ah, const float* Al, const float* Bh, const float* Bl,
    int i0, int j0, int K, int kc, int tid)
{
    const int kofs = kc * 32;
    const float* srcs[4] = { Ah, Al, Bh, Bl };
#pragma unroll
    for (int tile = 0; tile < 4; tile++) {
        const float* src = srcs[tile];
        const int rbase = (tile < 2) ? i0 : j0;
        uint32_t tb = sbase + (uint32_t)(stage * 4 + tile) * TILE_B;
#pragma unroll
        for (int it = 0; it < 4; it++) {
            int idx = tid + it * 256;
            int row = idx >> 3;
            int c4  = idx & 7;
            cp16(tb + (uint32_t)(row * (SSTR * 4) + c4 * 16),
                 src + (size_t)(rbase + row) * K + kofs + c4 * 4);
        }
    }
}

__global__ __launch_bounds__(256) void gemm_mma_split(
    const float* __restrict__ Ah, const float* __restrict__ Al,
    const float* __restrict__ Bh, const float* __restrict__ Bl,
    const float* __restrict__ bias, float* __restrict__ C,
    int M, int N, int K)
{
    extern __shared__ float sm[];
    const uint32_t sbase = smem_u32(sm);
    const int tid  = threadIdx.x;
    const int lane = tid & 31;
    const int wid  = tid >> 5;
    const int wm   = wid & 1;
    const int wn   = wid >> 1;
    const int g    = lane >> 2;
    const int t4   = lane & 3;
    const int i0 = blockIdx.y * 128, j0 = blockIdx.x * 128;
    const int nk = K / 32;

    float acc[16][4];
#pragma unroll
    for (int i = 0; i < 16; i++)
#pragma unroll
        for (int j = 0; j < 4; j++) acc[i][j] = 0.f;

    g_load_chunk(sbase, 0, Ah, Al, Bh, Bl, i0, j0, K, 0, tid); cp_commit();
    g_load_chunk(sbase, 1, Ah, Al, Bh, Bl, i0, j0, K, 1, tid); cp_commit();

    for (int kc = 0; kc < nk; kc++) {
        const int s = kc & 1;
        if (kc + 2 < nk) cp_wait<1>(); else cp_wait<0>();
        __syncthreads();

        const uint32_t* sAh = (const uint32_t*)(sm + (s * 4 + 0) * TILE_F);
        const uint32_t* sAl = (const uint32_t*)(sm + (s * 4 + 1) * TILE_F);
        const uint32_t* sBh = (const uint32_t*)(sm + (s * 4 + 2) * TILE_F);
        const uint32_t* sBl = (const uint32_t*)(sm + (s * 4 + 3) * TILE_F);

#pragma unroll
        for (int ks = 0; ks < 4; ks++) {
            const int kcol = ks * 8 + t4;
            uint32_t ah[4][4], al[4][4], bh[4][2], bl[4][2];
#pragma unroll
            for (int mt = 0; mt < 4; mt++) {
                int base = (wm * 64 + mt * 16 + g) * SSTR + kcol;
                ah[mt][0] = sAh[base];
                ah[mt][1] = sAh[base + 8 * SSTR];
                ah[mt][2] = sAh[base + 4];
                ah[mt][3] = sAh[base + 8 * SSTR + 4];
                al[mt][0] = sAl[base];
                al[mt][1] = sAl[base + 8 * SSTR];
                al[mt][2] = sAl[base + 4];
                al[mt][3] = sAl[base + 8 * SSTR + 4];
            }
#pragma unroll
            for (int nt = 0; nt < 4; nt++) {
                int base = (wn * 32 + nt * 8 + g) * SSTR + kcol;
                bh[nt][0] = sBh[base];
                bh[nt][1] = sBh[base + 4];
                bl[nt][0] = sBl[base];
                bl[nt][1] = sBl[base + 4];
            }
#pragma unroll
            for (int mt = 0; mt < 4; mt++)
#pragma unroll
                for (int nt = 0; nt < 4; nt++) {
                    float* d = acc[mt * 4 + nt];
                    mma1688(d, ah[mt], bh[nt]);
                    mma1688(d, ah[mt], bl[nt]);
                    mma1688(d, al[mt], bh[nt]);
                }
        }
        __syncthreads();
        if (kc + 2 < nk) {
            g_load_chunk(sbase, s, Ah, Al, Bh, Bl, i0, j0, K, kc + 2, tid);
            cp_commit();
        }
    }

#pragma unroll
    for (int mt = 0; mt < 4; mt++) {
#pragma unroll
        for (int nt = 0; nt < 4; nt++) {
            const float* d = acc[mt * 4 + nt];
            int row = i0 + wm * 64 + mt * 16 + g;
            int col = j0 + wn * 32 + nt * 8 + 2 * t4;
            float b0 = bias[col], b1 = bias[col + 1];
            float2 v0 = { d[0] + b0, d[1] + b1 };
            float2 v1 = { d[2] + b0, d[3] + b1 };
            *reinterpret_cast<float2*>(C + (size_t)row * N + col) = v0;
            *reinterpret_cast<float2*>(C + (size_t)(row + 8) * N + col) = v1;
        }
    }
}

// ---------------------------------------------------------------------------
// Tensor-core flash attention, pure tf32 3-product split, fp32 smem tiles.
// 256 threads = 8 warps. Warps 0-3 ("S-warps"): S = Q K^T, softmax, O += P V
// for q-rows [16w, 16w+16). Warps 4-7 ("R-warps"): banded R = Q ErBand^T for
// the same row group, plus all cp.async loads.
// Fragment index patterns are copies of the validated GEMM above.
// ---------------------------------------------------------------------------
constexpr int ASTR = 68;                    // fp32 tile row stride (floats)
constexpr int RSTR = 132;
constexpr int O_Q  = 0;                     // 64x68
constexpr int O_K  = 4352;                  // 2 stages x 64x68
constexpr int O_V  = O_K + 2 * 4352;        // 13056
constexpr int O_E  = O_V + 2 * 4352;        // 21760, 2 stages x 128x68
constexpr int O_P  = O_E + 2 * 8704;        // 39168
constexpr int O_SR = O_P + 4352;            // 43520
constexpr int ATTN_FLOATS = O_SR + 64 * RSTR;   // 51968
constexpr int ATTN_SMEM   = ATTN_FLOATS * 4;    // 207872

__global__ __launch_bounds__(256) void attn_tc(
    const float* __restrict__ qkv, const float* __restrict__ Er,
    float* __restrict__ y)
{
    extern __shared__ float sf[];
    const uint32_t sb = smem_u32(sf);

    const int qt = blockIdx.x, bhid = blockIdx.y;
    const int b = bhid >> 4, h = bhid & 15;
    const int i0 = qt * 64;
    const int tid = threadIdx.x, lane = tid & 31, wid = tid >> 5;
    const int role = wid >> 2;         // 0 = S-warp, 1 = R/loader-warp
    const int sw = wid & 3;            // row group
    const int qr = sw * 16;
    const int g = lane >> 2, t4 = lane & 3;
    const int t128 = tid & 127;

    // -------- loaders --------
    auto load_kve = [&](int stg, int kt) {
        const int j0 = kt * 64;
        const float* kg = qkv + ((size_t)(b * Lc + j0)) * TDc + Dc + h * 64;
        const float* vg = kg + Dc;
        uint32_t kb = sb + (uint32_t)(O_K + stg * 4352) * 4;
        uint32_t vb = sb + (uint32_t)(O_V + stg * 4352) * 4;
#pragma unroll
        for (int t = 0; t < 8; t++) {
            int idx = t128 + t * 128;      // 0..1023
            int row = idx >> 4, c = idx & 15;
            cp16(kb + (uint32_t)(row * ASTR + c * 4) * 4, kg + (size_t)row * TDc + c * 4);
            cp16(vb + (uint32_t)(row * ASTR + c * 4) * 4, vg + (size_t)row * TDc + c * 4);
        }
        const int mbase = Lc - 64 - i0 + j0;   // >= 0
        uint32_t eb = sb + (uint32_t)(O_E + stg * 8704) * 4;
#pragma unroll
        for (int t = 0; t < 16; t++) {
            int idx = t128 + t * 128;      // 0..2047
            int row = idx >> 4, c = idx & 15;
            int m = mbase + row; m = m < (Lc - 1) ? m : (Lc - 1);
            cp16(eb + (uint32_t)(row * ASTR + c * 4) * 4, Er + (size_t)m * HSc + c * 4);
        }
    };

    if (role == 1) {
        // Q tile
        const float* qg = qkv + ((size_t)(b * Lc + i0)) * TDc + h * 64;
#pragma unroll
        for (int t = 0; t < 8; t++) {
            int idx = t128 + t * 128;
            int row = idx >> 4, c = idx & 15;
            cp16(sb + (uint32_t)(O_Q + row * ASTR + c * 4) * 4, qg + (size_t)row * TDc + c * 4);
        }
        load_kve(0, 0);
        cp_commit();
    }

    uint32_t aQh[8][4], aQl[8][4];
    float cO[8][4];
    float m0 = -INFINITY, m1 = -INFINITY, l0 = 0.f, l1 = 0.f;
#pragma unroll
    for (int i = 0; i < 8; i++)
#pragma unroll
        for (int j = 0; j < 4; j++) cO[i][j] = 0.f;

    float* sP  = sf + O_P;
    float* sR  = sf + O_SR;

    for (int kt = 0; kt <= qt; kt++) {
        cp_wait<0>();          // loaders: stage kt arrived (S-warps trivially pass)
        __syncthreads();       // B1: stage + (kt==0) Q visible; prev gather done

        if (kt == 0) {
            // Q a-frags (GEMM A pattern), hi/lo in registers
#pragma unroll
            for (int ks = 0; ks < 8; ks++) {
                int base = (qr + g) * ASTR + 8 * ks + t4;
                float a0 = sf[O_Q + base];
                float a1 = sf[O_Q + base + 8 * ASTR];
                float a2 = sf[O_Q + base + 4];
                float a3 = sf[O_Q + base + 8 * ASTR + 4];
                float h0 = tf32_hi(a0), h1 = tf32_hi(a1), h2 = tf32_hi(a2), h3 = tf32_hi(a3);
                aQh[ks][0] = __float_as_uint(h0);
                aQh[ks][1] = __float_as_uint(h1);
                aQh[ks][2] = __float_as_uint(h2);
                aQh[ks][3] = __float_as_uint(h3);
                aQl[ks][0] = __float_as_uint(a0 - h0);
                aQl[ks][1] = __float_as_uint(a1 - h1);
                aQl[ks][2] = __float_as_uint(a2 - h2);
                aQl[ks][3] = __float_as_uint(a3 - h3);
            }
        }

        const int stg = kt & 1;
        const float* sK = sf + O_K + stg * 4352;
        const float* sV = sf + O_V + stg * 4352;
        const float* sE = sf + O_E + stg * 8704;

        float cS[8][4];
        if (role == 1) {
            // ---- R = Q * ErBand^T over the needed 10 n-blocks ----
            const int nt0 = 6 - 2 * sw;
#pragma unroll
            for (int i = 0; i < 10; i++) {
                const int nt = nt0 + i;
                float acc[4] = {0.f, 0.f, 0.f, 0.f};
#pragma unroll
                for (int ks = 0; ks < 8; ks++) {
                    int base = (nt * 8 + g) * ASTR + 8 * ks + t4;
                    mma3(acc, aQh[ks], aQl[ks], sE[base], sE[base + 4]);
                }
                int col = nt * 8 + 2 * t4;
                *(float2*)&sR[(qr + g) * RSTR + col]     = make_float2(acc[0], acc[1]);
                *(float2*)&sR[(qr + g + 8) * RSTR + col] = make_float2(acc[2], acc[3]);
            }
        } else {
            // ---- S = Q * K^T ----
#pragma unroll
            for (int nt = 0; nt < 8; nt++) {
                cS[nt][0] = cS[nt][1] = cS[nt][2] = cS[nt][3] = 0.f;
            }
#pragma unroll
            for (int ks = 0; ks < 8; ks++) {
#pragma unroll
                for (int nt = 0; nt < 8; nt++) {
                    int base = (nt * 8 + g) * ASTR + 8 * ks + t4;
                    mma3(cS[nt], aQh[ks], aQl[ks], sK[base], sK[base + 4]);
                }
            }
        }

        __syncthreads();       // B2: sR ready

        if (role == 0) {
            // ---- gather Srel + scale + causal mask ----
            const float scale = 0.125f;
            const bool diag = (kt == qt);
            const int r0 = qr + g, r1 = qr + g + 8;
            float rm0 = -INFINITY, rm1 = -INFINITY;
#pragma unroll
            for (int nt = 0; nt < 8; nt++) {
                int jl = nt * 8 + 2 * t4;
                int jj0 = 63 + jl - r0;
                int jj1 = 63 + jl - r1;
                float s0 = (cS[nt][0] + sR[r0 * RSTR + jj0]) * scale;
                float s1 = (cS[nt][1] + sR[r0 * RSTR + jj0 + 1]) * scale;
                float s2 = (cS[nt][2] + sR[r1 * RSTR + jj1]) * scale;
                float s3 = (cS[nt][3] + sR[r1 * RSTR + jj1 + 1]) * scale;
                if (diag) {
                    if (jl     > r0) s0 = -INFINITY;
                    if (jl + 1 > r0) s1 = -INFINITY;
                    if (jl     > r1) s2 = -INFINITY;
                    if (jl + 1 > r1) s3 = -INFINITY;
                }
                cS[nt][0] = s0; cS[nt][1] = s1; cS[nt][2] = s2; cS[nt][3] = s3;
                rm0 = fmaxf(rm0, fmaxf(s0, s1));
                rm1 = fmaxf(rm1, fmaxf(s2, s3));
            }
            rm0 = fmaxf(rm0, __shfl_xor_sync(0xFFFFFFFFu, rm0, 1));
            rm0 = fmaxf(rm0, __shfl_xor_sync(0xFFFFFFFFu, rm0, 2));
            rm1 = fmaxf(rm1, __shfl_xor_sync(0xFFFFFFFFu, rm1, 1));
            rm1 = fmaxf(rm1, __shfl_xor_sync(0xFFFFFFFFu, rm1, 2));
            float mn0 = fmaxf(m0, rm0), mn1 = fmaxf(m1, rm1);
            float al0 = __expf(m0 - mn0), al1 = __expf(m1 - mn1);

            // ---- exp, row sums, P -> smem (c-frag positions) ----
            float sum0 = 0.f, sum1 = 0.f;
#pragma unroll
            for (int nt = 0; nt < 8; nt++) {
                float p0 = __expf(cS[nt][0] - mn0);
                float p1 = __expf(cS[nt][1] - mn0);
                float p2 = __expf(cS[nt][2] - mn1);
                float p3 = __expf(cS[nt][3] - mn1);
                sum0 += p0 + p1; sum1 += p2 + p3;
                int col = nt * 8 + 2 * t4;
                *(float2*)&sP[r0 * ASTR + col] = make_float2(p0, p1);
                *(float2*)&sP[r1 * ASTR + col] = make_float2(p2, p3);
            }
            sum0 += __shfl_xor_sync(0xFFFFFFFFu, sum0, 1);
            sum0 += __shfl_xor_sync(0xFFFFFFFFu, sum0, 2);
            sum1 += __shfl_xor_sync(0xFFFFFFFFu, sum1, 1);
            sum1 += __shfl_xor_sync(0xFFFFFFFFu, sum1, 2);
            l0 = l0 * al0 + sum0;
            l1 = l1 * al1 + sum1;
            m0 = mn0; m1 = mn1;
#pragma unroll
            for (int nt = 0; nt < 8; nt++) {
                cO[nt][0] *= al0; cO[nt][1] *= al0;
                cO[nt][2] *= al1; cO[nt][3] *= al1;
            }
            __syncwarp();

            // ---- O += P * V ----
#pragma unroll
            for (int ks = 0; ks < 8; ks++) {
                int pb = (qr + g) * ASTR + 8 * ks + t4;
                float p0 = sP[pb];
                float p1 = sP[pb + 8 * ASTR];
                float p2 = sP[pb + 4];
                float p3 = sP[pb + 8 * ASTR + 4];
                float h0 = tf32_hi(p0), h1 = tf32_hi(p1), h2 = tf32_hi(p2), h3 = tf32_hi(p3);
                uint32_t ph[4] = { __float_as_uint(h0), __float_as_uint(h1),
                                   __float_as_uint(h2), __float_as_uint(h3) };
                uint32_t pl[4] = { __float_as_uint(p0 - h0), __float_as_uint(p1 - h1),
                                   __float_as_uint(p2 - h2), __float_as_uint(p3 - h3) };
#pragma unroll
                for (int nt = 0; nt < 8; nt++) {
                    float v0 = sV[(8 * ks + t4) * ASTR + nt * 8 + g];
                    float v1 = sV[(8 * ks + t4 + 4) * ASTR + nt * 8 + g];
                    mma3(cO[nt], ph, pl, v0, v1);
                }
            }
        } else if (kt < qt) {
            load_kve(stg ^ 1, kt + 1);
            cp_commit();
        }
    }

    // ---- epilogue (S-warps) ----
    if (role == 0) {
        float inv0 = 1.f / l0, inv1 = 1.f / l1;
        const int row0 = i0 + qr + g, row1 = row0 + 8;
#pragma unroll
        for (int nt = 0; nt < 8; nt++) {
            int d = nt * 8 + 2 * t4;
            float2 v0 = make_float2(cO[nt][0] * inv0, cO[nt][1] * inv0);
            float2 v1 = make_float2(cO[nt][2] * inv1, cO[nt][3] * inv1);
            *(float2*)&y[((size_t)(b * Lc + row0)) * Dc + h * 64 + d] = v0;
            *(float2*)&y[((size_t)(b * Lc + row1)) * Dc + h * 64 + d] = v1;
        }
    }
}

// ---------------------------------------------------------------------------
extern "C" void kernel_launch(void* const* d_in, const int* in_sizes, int n_in,
                              void* d_out, int out_size)
{
    const float* x     = (const float*)d_in[0];
    const float* Wqkv  = (const float*)d_in[1];
    const float* bqkv  = (const float*)d_in[2];
    const float* Wproj = (const float*)d_in[3];
    const float* bproj = (const float*)d_in[4];
    const float* Er    = (const float*)d_in[5];
    float* out = (float*)d_out;

    float *xh, *xl, *wqh, *wql, *wph, *wpl, *qkvp, *yp, *yh, *yl;
    cudaGetSymbolAddress((void**)&xh, g_xh);
    cudaGetSymbolAddress((void**)&xl, g_xl);
    cudaGetSymbolAddress((void**)&wqh, g_wqkvt_h);
    cudaGetSymbolAddress((void**)&wql, g_wqkvt_l);
    cudaGetSymbolAddress((void**)&wph, g_wprojt_h);
    cudaGetSymbolAddress((void**)&wpl, g_wprojt_l);
    cudaGetSymbolAddress((void**)&qkvp, g_qkv);
    cudaGetSymbolAddress((void**)&yp, g_y);
    cudaGetSymbolAddress((void**)&yh, g_yh);
    cudaGetSymbolAddress((void**)&yl, g_yl);

    cudaFuncSetAttribute(gemm_mma_split,
                         cudaFuncAttributeMaxDynamicSharedMemorySize, (int)GSMEM);
    cudaFuncSetAttribute(attn_tc,
                         cudaFuncAttributeMaxDynamicSharedMemorySize, ATTN_SMEM);

    int n4x = Mrows * Dc / 4;
    split_tf32<<<(n4x + 255) / 256, 256>>>(x, xh, xl, n4x);
    transpose_split<<<dim3(TDc / 32, Dc / 32), dim3(32, 8)>>>(Wqkv, wqh, wql, Dc, TDc);
    transpose_split<<<dim3(Dc / 32, Dc / 32), dim3(32, 8)>>>(Wproj, wph, wpl, Dc, Dc);

    // qkv = x @ Wqkv + bqkv
    gemm_mma_split<<<dim3(TDc / 128, Mrows / 128), 256, GSMEM>>>(
        xh, xl, wqh, wql, bqkv, qkvp, Mrows, TDc, Dc);

    // tensor-core flash attention (reads fp32 qkv + Er directly)
    attn_tc<<<dim3(Lc / 64, Bc * NHc), 256, ATTN_SMEM>>>(qkvp, Er, yp);

    // out = y @ Wproj + bproj
    split_tf32<<<(n4x + 255) / 256, 256>>>(yp, yh, yl, n4x);
    gemm_mma_split<<<dim3(Dc / 128, Mrows / 128), 256, GSMEM>>>(
        yh, yl, wph, wpl, bproj, out, Mrows, Dc, Dc);
}

// round 9
// speedup vs baseline: 1.5813x; 1.0997x over previous
#include <cuda_runtime.h>
#include <cstdint>
#include <math.h>

// Problem constants
constexpr int Bc  = 2;
constexpr int Lc  = 2048;
constexpr int Dc  = 1024;
constexpr int NHc = 16;
constexpr int HSc = 64;
constexpr int TDc = 3 * Dc;       // 3072
constexpr int Mrows = Bc * Lc;    // 4096

// ---------------- static scratch (no allocation allowed) ----------------
__device__ float g_wqkvt[(size_t)TDc * Dc];   // Wqkv^T [3072,1024]
__device__ float g_wprojt[(size_t)Dc * Dc];   // Wproj^T [1024,1024]
__device__ float g_qkv[(size_t)Mrows * TDc];
__device__ float g_y[(size_t)Mrows * Dc];

// ---------------- helpers ----------------
__device__ __forceinline__ uint32_t smem_u32(const void* p) {
    uint32_t a;
    asm("{ .reg .u64 t; cvta.to.shared.u64 t, %1; cvt.u32.u64 %0, t; }"
        : "=r"(a) : "l"(p));
    return a;
}
__device__ __forceinline__ void cp16(uint32_t saddr, const void* g) {
    asm volatile("cp.async.cg.shared.global [%0], [%1], 16;" :: "r"(saddr), "l"(g));
}
__device__ __forceinline__ void cp_commit() { asm volatile("cp.async.commit_group;"); }
template <int N> __device__ __forceinline__ void cp_wait() {
    asm volatile("cp.async.wait_group %0;" :: "n"(N));
}
__device__ __forceinline__ float tf32_hi(float a) {
    return __uint_as_float(__float_as_uint(a) & 0xFFFFE000u);
}
__device__ __forceinline__ void mma1688b(float* d, const uint32_t* a,
                                         uint32_t b0, uint32_t b1) {
    asm volatile(
        "mma.sync.aligned.m16n8k8.row.col.f32.tf32.tf32.f32 "
        "{%0,%1,%2,%3}, {%4,%5,%6,%7}, {%8,%9}, {%0,%1,%2,%3};"
        : "+f"(d[0]), "+f"(d[1]), "+f"(d[2]), "+f"(d[3])
        : "r"(a[0]), "r"(a[1]), "r"(a[2]), "r"(a[3]), "r"(b0), "r"(b1));
}
// 3-product tf32 split: d += a*b; a as pre-split hi/lo frags, b split here.
__device__ __forceinline__ void mma3(float* d, const uint32_t* ah, const uint32_t* al,
                                     float b0, float b1) {
    float b0h = tf32_hi(b0), b1h = tf32_hi(b1);
    uint32_t B0h = __float_as_uint(b0h), B1h = __float_as_uint(b1h);
    uint32_t B0l = __float_as_uint(b0 - b0h), B1l = __float_as_uint(b1 - b1h);
    mma1688b(d, ah, B0h, B1h);
    mma1688b(d, ah, B0l, B1l);
    mma1688b(d, al, B0h, B1h);
}

// ---------------- transpose pre-pass: W [K,N] -> T [N,K] ----------------
__global__ __launch_bounds__(256) void transpose_k(
    const float* __restrict__ W, float* __restrict__ T, int K, int N)
{
    __shared__ float t[32][33];
    int n0 = blockIdx.x * 32, k0 = blockIdx.y * 32;
    int tx = threadIdx.x, ty = threadIdx.y;   // 32 x 8
#pragma unroll
    for (int r = 0; r < 4; r++)
        t[ty + 8 * r][tx] = W[(size_t)(k0 + ty + 8 * r) * N + n0 + tx];
    __syncthreads();
#pragma unroll
    for (int r = 0; r < 4; r++)
        T[(size_t)(n0 + ty + 8 * r) * K + k0 + tx] = t[tx][ty + 8 * r];
}

// ---------------- tf32 split GEMM, register hi/lo split ----------------
// C[M,N] = A[M,K] @ Bt[N,K]^T + bias. CTA 128x128, BK=32, 8 warps,
// double-buffered cp.async, 2 CTAs/SM.
constexpr int SSTR   = 36;
constexpr int TILE_F = 128 * SSTR;        // floats per 128x32 tile
constexpr int TILE_B = TILE_F * 4;        // 18432 bytes
constexpr uint32_t GSMEM = 2u * 2u * TILE_B;  // 2 stages * {A,B} = 73728

__device__ __forceinline__ void g_load_chunk(
    uint32_t sbase, int stage, const float* A, const float* Bt,
    int i0, int j0, int K, int kc, int tid)
{
    const int kofs = kc * 32;
#pragma unroll
    for (int tile = 0; tile < 2; tile++) {
        const float* src = tile ? Bt : A;
        const int rbase = tile ? j0 : i0;
        uint32_t tb = sbase + (uint32_t)(stage * 2 + tile) * TILE_B;
#pragma unroll
        for (int it = 0; it < 4; it++) {
            int idx = tid + it * 256;   // 0..1023
            int row = idx >> 3;         // 0..127
            int c4  = idx & 7;          // 0..7
            cp16(tb + (uint32_t)(row * (SSTR * 4) + c4 * 16),
                 src + (size_t)(rbase + row) * K + kofs + c4 * 4);
        }
    }
}

__global__ __launch_bounds__(256, 2) void gemm_tc(
    const float* __restrict__ A, const float* __restrict__ Bt,
    const float* __restrict__ bias, float* __restrict__ C,
    int M, int N, int K)
{
    extern __shared__ float sm[];
    const uint32_t sbase = smem_u32(sm);
    const int tid  = threadIdx.x;
    const int lane = tid & 31;
    const int wid  = tid >> 5;
    const int wm   = wid & 1;      // warp row -> 64 rows
    const int wn   = wid >> 1;     // warp col -> 32 cols
    const int g    = lane >> 2;
    const int t4   = lane & 3;
    const int i0 = blockIdx.y * 128, j0 = blockIdx.x * 128;
    const int nk = K / 32;

    float acc[16][4];
#pragma unroll
    for (int i = 0; i < 16; i++)
#pragma unroll
        for (int j = 0; j < 4; j++) acc[i][j] = 0.f;

    g_load_chunk(sbase, 0, A, Bt, i0, j0, K, 0, tid); cp_commit();
    g_load_chunk(sbase, 1, A, Bt, i0, j0, K, 1, tid); cp_commit();

    for (int kc = 0; kc < nk; kc++) {
        const int s = kc & 1;
        if (kc + 2 < nk) cp_wait<1>(); else cp_wait<0>();
        __syncthreads();

        const float* sA = sm + (s * 2 + 0) * TILE_F;
        const float* sB = sm + (s * 2 + 1) * TILE_F;

#pragma unroll
        for (int ks = 0; ks < 4; ks++) {
            const int kcol = ks * 8 + t4;
            // A frags: hi/lo split in registers (validated pattern)
            uint32_t ah[4][4], al[4][4];
#pragma unroll
            for (int mt = 0; mt < 4; mt++) {
                int base = (wm * 64 + mt * 16 + g) * SSTR + kcol;
                float a0 = sA[base];
                float a1 = sA[base + 8 * SSTR];
                float a2 = sA[base + 4];
                float a3 = sA[base + 8 * SSTR + 4];
                float h0 = tf32_hi(a0), h1 = tf32_hi(a1);
                float h2 = tf32_hi(a2), h3 = tf32_hi(a3);
                ah[mt][0] = __float_as_uint(h0);
                ah[mt][1] = __float_as_uint(h1);
                ah[mt][2] = __float_as_uint(h2);
                ah[mt][3] = __float_as_uint(h3);
                al[mt][0] = __float_as_uint(a0 - h0);
                al[mt][1] = __float_as_uint(a1 - h1);
                al[mt][2] = __float_as_uint(a2 - h2);
                al[mt][3] = __float_as_uint(a3 - h3);
            }
#pragma unroll
            for (int nt = 0; nt < 4; nt++) {
                int base = (wn * 32 + nt * 8 + g) * SSTR + kcol;
                float b0 = sB[base];
                float b1 = sB[base + 4];
                float b0h = tf32_hi(b0), b1h = tf32_hi(b1);
                uint32_t B0h = __float_as_uint(b0h), B1h = __float_as_uint(b1h);
                uint32_t B0l = __float_as_uint(b0 - b0h), B1l = __float_as_uint(b1 - b1h);
#pragma unroll
                for (int mt = 0; mt < 4; mt++) {
                    float* d = acc[mt * 4 + nt];
                    mma1688b(d, ah[mt], B0h, B1h);
                    mma1688b(d, ah[mt], B0l, B1l);
                    mma1688b(d, al[mt], B0h, B1h);
                }
            }
        }
        __syncthreads();
        if (kc + 2 < nk) {
            g_load_chunk(sbase, s, A, Bt, i0, j0, K, kc + 2, tid);
            cp_commit();
        }
    }

#pragma unroll
    for (int mt = 0; mt < 4; mt++) {
#pragma unroll
        for (int nt = 0; nt < 4; nt++) {
            const float* d = acc[mt * 4 + nt];
            int row = i0 + wm * 64 + mt * 16 + g;
            int col = j0 + wn * 32 + nt * 8 + 2 * t4;
            float b0 = bias[col], b1 = bias[col + 1];
            float2 v0 = { d[0] + b0, d[1] + b1 };
            float2 v1 = { d[2] + b0, d[3] + b1 };
            *reinterpret_cast<float2*>(C + (size_t)row * N + col) = v0;
            *reinterpret_cast<float2*>(C + (size_t)(row + 8) * N + col) = v1;
        }
    }
}

// ---------------------------------------------------------------------------
// Tensor-core flash attention (passing R7 version, unchanged).
// ---------------------------------------------------------------------------
constexpr int ASTR = 68;
constexpr int RSTR = 132;
constexpr int O_Q  = 0;
constexpr int O_K  = 4352;
constexpr int O_V  = O_K + 2 * 4352;
constexpr int O_E  = O_V + 2 * 4352;
constexpr int O_P  = O_E + 2 * 8704;
constexpr int O_SR = O_P + 4352;
constexpr int ATTN_FLOATS = O_SR + 64 * RSTR;
constexpr int ATTN_SMEM   = ATTN_FLOATS * 4;

__global__ __launch_bounds__(256) void attn_tc(
    const float* __restrict__ qkv, const float* __restrict__ Er,
    float* __restrict__ y)
{
    extern __shared__ float sf[];
    const uint32_t sb = smem_u32(sf);

    const int qt = blockIdx.x, bhid = blockIdx.y;
    const int b = bhid >> 4, h = bhid & 15;
    const int i0 = qt * 64;
    const int tid = threadIdx.x, lane = tid & 31, wid = tid >> 5;
    const int role = wid >> 2;
    const int sw = wid & 3;
    const int qr = sw * 16;
    const int g = lane >> 2, t4 = lane & 3;
    const int t128 = tid & 127;

    auto load_kve = [&](int stg, int kt) {
        const int j0 = kt * 64;
        const float* kg = qkv + ((size_t)(b * Lc + j0)) * TDc + Dc + h * 64;
        const float* vg = kg + Dc;
        uint32_t kb = sb + (uint32_t)(O_K + stg * 4352) * 4;
        uint32_t vb = sb + (uint32_t)(O_V + stg * 4352) * 4;
#pragma unroll
        for (int t = 0; t < 8; t++) {
            int idx = t128 + t * 128;
            int row = idx >> 4, c = idx & 15;
            cp16(kb + (uint32_t)(row * ASTR + c * 4) * 4, kg + (size_t)row * TDc + c * 4);
            cp16(vb + (uint32_t)(row * ASTR + c * 4) * 4, vg + (size_t)row * TDc + c * 4);
        }
        const int mbase = Lc - 64 - i0 + j0;
        uint32_t eb = sb + (uint32_t)(O_E + stg * 8704) * 4;
#pragma unroll
        for (int t = 0; t < 16; t++) {
            int idx = t128 + t * 128;
            int row = idx >> 4, c = idx & 15;
            int m = mbase + row; m = m < (Lc - 1) ? m : (Lc - 1);
            cp16(eb + (uint32_t)(row * ASTR + c * 4) * 4, Er + (size_t)m * HSc + c * 4);
        }
    };

    if (role == 1) {
        const float* qg = qkv + ((size_t)(b * Lc + i0)) * TDc + h * 64;
#pragma unroll
        for (int t = 0; t < 8; t++) {
            int idx = t128 + t * 128;
            int row = idx >> 4, c = idx & 15;
            cp16(sb + (uint32_t)(O_Q + row * ASTR + c * 4) * 4, qg + (size_t)row * TDc + c * 4);
        }
        load_kve(0, 0);
        cp_commit();
    }

    uint32_t aQh[8][4], aQl[8][4];
    float cO[8][4];
    float m0 = -INFINITY, m1 = -INFINITY, l0 = 0.f, l1 = 0.f;
#pragma unroll
    for (int i = 0; i < 8; i++)
#pragma unroll
        for (int j = 0; j < 4; j++) cO[i][j] = 0.f;

    float* sP  = sf + O_P;
    float* sR  = sf + O_SR;

    for (int kt = 0; kt <= qt; kt++) {
        cp_wait<0>();
        __syncthreads();

        if (kt == 0) {
#pragma unroll
            for (int ks = 0; ks < 8; ks++) {
                int base = (qr + g) * ASTR + 8 * ks + t4;
                float a0 = sf[O_Q + base];
                float a1 = sf[O_Q + base + 8 * ASTR];
                float a2 = sf[O_Q + base + 4];
                float a3 = sf[O_Q + base + 8 * ASTR + 4];
                float h0 = tf32_hi(a0), h1 = tf32_hi(a1), h2 = tf32_hi(a2), h3 = tf32_hi(a3);
                aQh[ks][0] = __float_as_uint(h0);
                aQh[ks][1] = __float_as_uint(h1);
                aQh[ks][2] = __float_as_uint(h2);
                aQh[ks][3] = __float_as_uint(h3);
                aQl[ks][0] = __float_as_uint(a0 - h0);
                aQl[ks][1] = __float_as_uint(a1 - h1);
                aQl[ks][2] = __float_as_uint(a2 - h2);
                aQl[ks][3] = __float_as_uint(a3 - h3);
            }
        }

        const int stg = kt & 1;
        const float* sK = sf + O_K + stg * 4352;
        const float* sV = sf + O_V + stg * 4352;
        const float* sE = sf + O_E + stg * 8704;

        float cS[8][4];
        if (role == 1) {
            const int nt0 = 6 - 2 * sw;
#pragma unroll
            for (int i = 0; i < 10; i++) {
                const int nt = nt0 + i;
                float acc[4] = {0.f, 0.f, 0.f, 0.f};
#pragma unroll
                for (int ks = 0; ks < 8; ks++) {
                    int base = (nt * 8 + g) * ASTR + 8 * ks + t4;
                    mma3(acc, aQh[ks], aQl[ks], sE[base], sE[base + 4]);
                }
                int col = nt * 8 + 2 * t4;
                *(float2*)&sR[(qr + g) * RSTR + col]     = make_float2(acc[0], acc[1]);
                *(float2*)&sR[(qr + g + 8) * RSTR + col] = make_float2(acc[2], acc[3]);
            }
        } else {
#pragma unroll
            for (int nt = 0; nt < 8; nt++) {
                cS[nt][0] = cS[nt][1] = cS[nt][2] = cS[nt][3] = 0.f;
            }
#pragma unroll
            for (int ks = 0; ks < 8; ks++) {
#pragma unroll
                for (int nt = 0; nt < 8; nt++) {
                    int base = (nt * 8 + g) * ASTR + 8 * ks + t4;
                    mma3(cS[nt], aQh[ks], aQl[ks], sK[base], sK[base + 4]);
                }
            }
        }

        __syncthreads();

        if (role == 0) {
            const float scale = 0.125f;
            const bool diag = (kt == qt);
            const int r0 = qr + g, r1 = qr + g + 8;
            float rm0 = -INFINITY, rm1 = -INFINITY;
#pragma unroll
            for (int nt = 0; nt < 8; nt++) {
                int jl = nt * 8 + 2 * t4;
                int jj0 = 63 + jl - r0;
                int jj1 = 63 + jl - r1;
                float s0 = (cS[nt][0] + sR[r0 * RSTR + jj0]) * scale;
                float s1 = (cS[nt][1] + sR[r0 * RSTR + jj0 + 1]) * scale;
                float s2 = (cS[nt][2] + sR[r1 * RSTR + jj1]) * scale;
                float s3 = (cS[nt][3] + sR[r1 * RSTR + jj1 + 1]) * scale;
                if (diag) {
                    if (jl     > r0) s0 = -INFINITY;
                    if (jl + 1 > r0) s1 = -INFINITY;
                    if (jl     > r1) s2 = -INFINITY;
                    if (jl + 1 > r1) s3 = -INFINITY;
                }
                cS[nt][0] = s0; cS[nt][1] = s1; cS[nt][2] = s2; cS[nt][3] = s3;
                rm0 = fmaxf(rm0, fmaxf(s0, s1));
                rm1 = fmaxf(rm1, fmaxf(s2, s3));
            }
            rm0 = fmaxf(rm0, __shfl_xor_sync(0xFFFFFFFFu, rm0, 1));
            rm0 = fmaxf(rm0, __shfl_xor_sync(0xFFFFFFFFu, rm0, 2));
            rm1 = fmaxf(rm1, __shfl_xor_sync(0xFFFFFFFFu, rm1, 1));
            rm1 = fmaxf(rm1, __shfl_xor_sync(0xFFFFFFFFu, rm1, 2));
            float mn0 = fmaxf(m0, rm0), mn1 = fmaxf(m1, rm1);
            float al0 = __expf(m0 - mn0), al1 = __expf(m1 - mn1);

            float sum0 = 0.f, sum1 = 0.f;
#pragma unroll
            for (int nt = 0; nt < 8; nt++) {
                float p0 = __expf(cS[nt][0] - mn0);
                float p1 = __expf(cS[nt][1] - mn0);
                float p2 = __expf(cS[nt][2] - mn1);
                float p3 = __expf(cS[nt][3] - mn1);
                sum0 += p0 + p1; sum1 += p2 + p3;
                int col = nt * 8 + 2 * t4;
                *(float2*)&sP[r0 * ASTR + col] = make_float2(p0, p1);
                *(float2*)&sP[r1 * ASTR + col] = make_float2(p2, p3);
            }
            sum0 += __shfl_xor_sync(0xFFFFFFFFu, sum0, 1);
            sum0 += __shfl_xor_sync(0xFFFFFFFFu, sum0, 2);
            sum1 += __shfl_xor_sync(0xFFFFFFFFu, sum1, 1);
            sum1 += __shfl_xor_sync(0xFFFFFFFFu, sum1, 2);
            l0 = l0 * al0 + sum0;
            l1 = l1 * al1 + sum1;
            m0 = mn0; m1 = mn1;
#pragma unroll
            for (int nt = 0; nt < 8; nt++) {
                cO[nt][0] *= al0; cO[nt][1] *= al0;
                cO[nt][2] *= al1; cO[nt][3] *= al1;
            }
            __syncwarp();

#pragma unroll
            for (int ks = 0; ks < 8; ks++) {
                int pb = (qr + g) * ASTR + 8 * ks + t4;
                float p0 = sP[pb];
                float p1 = sP[pb + 8 * ASTR];
                float p2 = sP[pb + 4];
                float p3 = sP[pb + 8 * ASTR + 4];
                float h0 = tf32_hi(p0), h1 = tf32_hi(p1), h2 = tf32_hi(p2), h3 = tf32_hi(p3);
                uint32_t ph[4] = { __float_as_uint(h0), __float_as_uint(h1),
                                   __float_as_uint(h2), __float_as_uint(h3) };
                uint32_t pl[4] = { __float_as_uint(p0 - h0), __float_as_uint(p1 - h1),
                                   __float_as_uint(p2 - h2), __float_as_uint(p3 - h3) };
#pragma unroll
                for (int nt = 0; nt < 8; nt++) {
                    float v0 = sV[(8 * ks + t4) * ASTR + nt * 8 + g];
                    float v1 = sV[(8 * ks + t4 + 4) * ASTR + nt * 8 + g];
                    mma3(cO[nt], ph, pl, v0, v1);
                }
            }
        } else if (kt < qt) {
            load_kve(stg ^ 1, kt + 1);
            cp_commit();
        }
    }

    if (role == 0) {
        float inv0 = 1.f / l0, inv1 = 1.f / l1;
        const int row0 = i0 + qr + g, row1 = row0 + 8;
#pragma unroll
        for (int nt = 0; nt < 8; nt++) {
            int d = nt * 8 + 2 * t4;
            float2 v0 = make_float2(cO[nt][0] * inv0, cO[nt][1] * inv0);
            float2 v1 = make_float2(cO[nt][2] * inv1, cO[nt][3] * inv1);
            *(float2*)&y[((size_t)(b * Lc + row0)) * Dc + h * 64 + d] = v0;
            *(float2*)&y[((size_t)(b * Lc + row1)) * Dc + h * 64 + d] = v1;
        }
    }
}

// ---------------------------------------------------------------------------
extern "C" void kernel_launch(void* const* d_in, const int* in_sizes, int n_in,
                              void* d_out, int out_size)
{
    const float* x     = (const float*)d_in[0];
    const float* Wqkv  = (const float*)d_in[1];
    const float* bqkv  = (const float*)d_in[2];
    const float* Wproj = (const float*)d_in[3];
    const float* bproj = (const float*)d_in[4];
    const float* Er    = (const float*)d_in[5];
    float* out = (float*)d_out;

    float *wqt, *wpt, *qkvp, *yp;
    cudaGetSymbolAddress((void**)&wqt, g_wqkvt);
    cudaGetSymbolAddress((void**)&wpt, g_wprojt);
    cudaGetSymbolAddress((void**)&qkvp, g_qkv);
    cudaGetSymbolAddress((void**)&yp, g_y);

    cudaFuncSetAttribute(gemm_tc,
                         cudaFuncAttributeMaxDynamicSharedMemorySize, (int)GSMEM);
    cudaFuncSetAttribute(attn_tc,
                         cudaFuncAttributeMaxDynamicSharedMemorySize, ATTN_SMEM);

    // transpose weights to [N,K]
    transpose_k<<<dim3(TDc / 32, Dc / 32), dim3(32, 8)>>>(Wqkv, wqt, Dc, TDc);
    transpose_k<<<dim3(Dc / 32, Dc / 32), dim3(32, 8)>>>(Wproj, wpt, Dc, Dc);

    // qkv = x @ Wqkv + bqkv
    gemm_tc<<<dim3(TDc / 128, Mrows / 128), 256, GSMEM>>>(
        x, wqt, bqkv, qkvp, Mrows, TDc, Dc);

    // tensor-core flash attention
    attn_tc<<<dim3(Lc / 64, Bc * NHc), 256, ATTN_SMEM>>>(qkvp, Er, yp);

    // out = y @ Wproj + bproj
    gemm_tc<<<dim3(Dc / 128, Mrows / 128), 256, GSMEM>>>(
        yp, wpt, bproj, out, Mrows, Dc, Dc);
}

// round 10
// speedup vs baseline: 1.6566x; 1.0476x over previous
#include <cuda_runtime.h>
#include <cstdint>
#include <math.h>

// Problem constants
constexpr int Bc  = 2;
constexpr int Lc  = 2048;
constexpr int Dc  = 1024;
constexpr int NHc = 16;
constexpr int HSc = 64;
constexpr int TDc = 3 * Dc;       // 3072
constexpr int Mrows = Bc * Lc;    // 4096

// ---------------- static scratch (no allocation allowed) ----------------
__device__ float g_wqkvt[(size_t)TDc * Dc];   // Wqkv^T [3072,1024]
__device__ float g_wprojt[(size_t)Dc * Dc];   // Wproj^T [1024,1024]
__device__ float g_qkv[(size_t)Mrows * TDc];
__device__ float g_y[(size_t)Mrows * Dc];

// ---------------- helpers ----------------
__device__ __forceinline__ uint32_t smem_u32(const void* p) {
    uint32_t a;
    asm("{ .reg .u64 t; cvta.to.shared.u64 t, %1; cvt.u32.u64 %0, t; }"
        : "=r"(a) : "l"(p));
    return a;
}
__device__ __forceinline__ void cp16(uint32_t saddr, const void* g) {
    asm volatile("cp.async.cg.shared.global [%0], [%1], 16;" :: "r"(saddr), "l"(g));
}
__device__ __forceinline__ void cp_commit() { asm volatile("cp.async.commit_group;"); }
template <int N> __device__ __forceinline__ void cp_wait() {
    asm volatile("cp.async.wait_group %0;" :: "n"(N));
}
__device__ __forceinline__ float tf32_hi(float a) {
    return __uint_as_float(__float_as_uint(a) & 0xFFFFE000u);
}
__device__ __forceinline__ float ex2(float x) {
    float r;
    asm("ex2.approx.f32 %0, %1;" : "=f"(r) : "f"(x));
    return r;
}
__device__ __forceinline__ void mma1688b(float* d, const uint32_t* a,
                                         uint32_t b0, uint32_t b1) {
    asm volatile(
        "mma.sync.aligned.m16n8k8.row.col.f32.tf32.tf32.f32 "
        "{%0,%1,%2,%3}, {%4,%5,%6,%7}, {%8,%9}, {%0,%1,%2,%3};"
        : "+f"(d[0]), "+f"(d[1]), "+f"(d[2]), "+f"(d[3])
        : "r"(a[0]), "r"(a[1]), "r"(a[2]), "r"(a[3]), "r"(b0), "r"(b1));
}
// 3-product tf32 split: d += a*b; a as pre-split hi/lo frags, b split here.
__device__ __forceinline__ void mma3(float* d, const uint32_t* ah, const uint32_t* al,
                                     float b0, float b1) {
    float b0h = tf32_hi(b0), b1h = tf32_hi(b1);
    uint32_t B0h = __float_as_uint(b0h), B1h = __float_as_uint(b1h);
    uint32_t B0l = __float_as_uint(b0 - b0h), B1l = __float_as_uint(b1 - b1h);
    mma1688b(d, ah, B0h, B1h);
    mma1688b(d, ah, B0l, B1l);
    mma1688b(d, al, B0h, B1h);
}

// ---------------- transpose pre-pass: W [K,N] -> T [N,K] ----------------
__global__ __launch_bounds__(256) void transpose_k(
    const float* __restrict__ W, float* __restrict__ T, int K, int N)
{
    __shared__ float t[32][33];
    int n0 = blockIdx.x * 32, k0 = blockIdx.y * 32;
    int tx = threadIdx.x, ty = threadIdx.y;   // 32 x 8
#pragma unroll
    for (int r = 0; r < 4; r++)
        t[ty + 8 * r][tx] = W[(size_t)(k0 + ty + 8 * r) * N + n0 + tx];
    __syncthreads();
#pragma unroll
    for (int r = 0; r < 4; r++)
        T[(size_t)(n0 + ty + 8 * r) * K + k0 + tx] = t[tx][ty + 8 * r];
}

// ---------------- tf32 split GEMM (passing R9 version, unchanged) ----------------
constexpr int SSTR   = 36;
constexpr int TILE_F = 128 * SSTR;
constexpr int TILE_B = TILE_F * 4;
constexpr uint32_t GSMEM = 2u * 2u * TILE_B;

__device__ __forceinline__ void g_load_chunk(
    uint32_t sbase, int stage, const float* A, const float* Bt,
    int i0, int j0, int K, int kc, int tid)
{
    const int kofs = kc * 32;
#pragma unroll
    for (int tile = 0; tile < 2; tile++) {
        const float* src = tile ? Bt : A;
        const int rbase = tile ? j0 : i0;
        uint32_t tb = sbase + (uint32_t)(stage * 2 + tile) * TILE_B;
#pragma unroll
        for (int it = 0; it < 4; it++) {
            int idx = tid + it * 256;
            int row = idx >> 3;
            int c4  = idx & 7;
            cp16(tb + (uint32_t)(row * (SSTR * 4) + c4 * 16),
                 src + (size_t)(rbase + row) * K + kofs + c4 * 4);
        }
    }
}

__global__ __launch_bounds__(256, 2) void gemm_tc(
    const float* __restrict__ A, const float* __restrict__ Bt,
    const float* __restrict__ bias, float* __restrict__ C,
    int M, int N, int K)
{
    extern __shared__ float sm[];
    const uint32_t sbase = smem_u32(sm);
    const int tid  = threadIdx.x;
    const int lane = tid & 31;
    const int wid  = tid >> 5;
    const int wm   = wid & 1;
    const int wn   = wid >> 1;
    const int g    = lane >> 2;
    const int t4   = lane & 3;
    const int i0 = blockIdx.y * 128, j0 = blockIdx.x * 128;
    const int nk = K / 32;

    float acc[16][4];
#pragma unroll
    for (int i = 0; i < 16; i++)
#pragma unroll
        for (int j = 0; j < 4; j++) acc[i][j] = 0.f;

    g_load_chunk(sbase, 0, A, Bt, i0, j0, K, 0, tid); cp_commit();
    g_load_chunk(sbase, 1, A, Bt, i0, j0, K, 1, tid); cp_commit();

    for (int kc = 0; kc < nk; kc++) {
        const int s = kc & 1;
        if (kc + 2 < nk) cp_wait<1>(); else cp_wait<0>();
        __syncthreads();

        const float* sA = sm + (s * 2 + 0) * TILE_F;
        const float* sB = sm + (s * 2 + 1) * TILE_F;

#pragma unroll
        for (int ks = 0; ks < 4; ks++) {
            const int kcol = ks * 8 + t4;
            uint32_t ah[4][4], al[4][4];
#pragma unroll
            for (int mt = 0; mt < 4; mt++) {
                int base = (wm * 64 + mt * 16 + g) * SSTR + kcol;
                float a0 = sA[base];
                float a1 = sA[base + 8 * SSTR];
                float a2 = sA[base + 4];
                float a3 = sA[base + 8 * SSTR + 4];
                float h0 = tf32_hi(a0), h1 = tf32_hi(a1);
                float h2 = tf32_hi(a2), h3 = tf32_hi(a3);
                ah[mt][0] = __float_as_uint(h0);
                ah[mt][1] = __float_as_uint(h1);
                ah[mt][2] = __float_as_uint(h2);
                ah[mt][3] = __float_as_uint(h3);
                al[mt][0] = __float_as_uint(a0 - h0);
                al[mt][1] = __float_as_uint(a1 - h1);
                al[mt][2] = __float_as_uint(a2 - h2);
                al[mt][3] = __float_as_uint(a3 - h3);
            }
#pragma unroll
            for (int nt = 0; nt < 4; nt++) {
                int base = (wn * 32 + nt * 8 + g) * SSTR + kcol;
                float b0 = sB[base];
                float b1 = sB[base + 4];
                float b0h = tf32_hi(b0), b1h = tf32_hi(b1);
                uint32_t B0h = __float_as_uint(b0h), B1h = __float_as_uint(b1h);
                uint32_t B0l = __float_as_uint(b0 - b0h), B1l = __float_as_uint(b1 - b1h);
#pragma unroll
                for (int mt = 0; mt < 4; mt++) {
                    float* d = acc[mt * 4 + nt];
                    mma1688b(d, ah[mt], B0h, B1h);
                    mma1688b(d, ah[mt], B0l, B1l);
                    mma1688b(d, al[mt], B0h, B1h);
                }
            }
        }
        __syncthreads();
        if (kc + 2 < nk) {
            g_load_chunk(sbase, s, A, Bt, i0, j0, K, kc + 2, tid);
            cp_commit();
        }
    }

#pragma unroll
    for (int mt = 0; mt < 4; mt++) {
#pragma unroll
        for (int nt = 0; nt < 4; nt++) {
            const float* d = acc[mt * 4 + nt];
            int row = i0 + wm * 64 + mt * 16 + g;
            int col = j0 + wn * 32 + nt * 8 + 2 * t4;
            float b0 = bias[col], b1 = bias[col + 1];
            float2 v0 = { d[0] + b0, d[1] + b1 };
            float2 v1 = { d[2] + b0, d[3] + b1 };
            *reinterpret_cast<float2*>(C + (size_t)row * N + col) = v0;
            *reinterpret_cast<float2*>(C + (size_t)(row + 8) * N + col) = v1;
        }
    }
}

// ---------------------------------------------------------------------------
// Tensor-core flash attention, rolling rel-pos buffer + k-split PV.
// 256 threads = 8 warps. Warp pair (w, w+4) owns q-rows [16w, 16w+16).
// S-warps (0-3): S-gemm, softmax, PV ks 0-3. R-warps (4-7): R-gemm of NEW
// band columns into rolling sR, prefetch loads, PV ks 4-7 (partial O2).
// Er smem = 256-slot ring (m & 255); sR = 128-slot ring (m & 127).
// ---------------------------------------------------------------------------
constexpr int ASTR  = 68;
constexpr int SRSTR = 136;
constexpr int O_Q  = 0;                     // 64 x 68
constexpr int O_K  = 4352;                  // 2 stages x 64 x 68
constexpr int O_V  = 13056;                 // 2 stages x 64 x 68
constexpr int O_E  = 21760;                 // 256 x 68 ring
constexpr int O_P  = 39168;                 // 64 x 68
constexpr int O_SR = 43520;                 // 64 x 136 ring
constexpr int O_AL = 52224;                 // 64 alphas
constexpr int ATTN_FLOATS = 52288;
constexpr int ATTN_SMEM   = ATTN_FLOATS * 4;   // 209152

__global__ __launch_bounds__(256) void attn_tc(
    const float* __restrict__ qkv, const float* __restrict__ Er,
    float* __restrict__ y)
{
    extern __shared__ float sf[];
    const uint32_t sb = smem_u32(sf);

    const int qt = blockIdx.x, bhid = blockIdx.y;
    const int b = bhid >> 4, h = bhid & 15;
    const int i0 = qt * 64;
    const int tid = threadIdx.x, lane = tid & 31, wid = tid >> 5;
    const int role = wid >> 2;          // 0 = S-warp, 1 = R-warp
    const int sw = wid & 3;             // row group
    const int qr = sw * 16;
    const int g = lane >> 2, t4 = lane & 3;
    const int t128 = tid & 127;
    const int mbase0 = Lc - 64 - i0;    // mbase at kt=0 (>= 0)

    float* sE  = sf + O_E;
    float* sP  = sf + O_P;
    float* sSR = sf + O_SR;
    float* sAL = sf + O_AL;

    // K/V stage load (R-warps)
    auto load_kv = [&](int stg, int kt) {
        const int j0 = kt * 64;
        const float* kg = qkv + ((size_t)(b * Lc + j0)) * TDc + Dc + h * 64;
        const float* vg = kg + Dc;
        uint32_t kb = sb + (uint32_t)(O_K + stg * 4352) * 4;
        uint32_t vb = sb + (uint32_t)(O_V + stg * 4352) * 4;
#pragma unroll
        for (int t = 0; t < 8; t++) {
            int idx = t128 + t * 128;
            int row = idx >> 4, c = idx & 15;
            cp16(kb + (uint32_t)(row * ASTR + c * 4) * 4, kg + (size_t)row * TDc + c * 4);
            cp16(vb + (uint32_t)(row * ASTR + c * 4) * 4, vg + (size_t)row * TDc + c * 4);
        }
    };
    // Er ring load: rows m in [mstart, mstart+cnt)
    auto load_e = [&](int mstart, int cnt) {
        for (int idx = t128; idx < cnt * 16; idx += 128) {
            int row = idx >> 4, c = idx & 15;
            int m = mstart + row;
            int slot = m & 255;
            int mc = m < (Lc - 1) ? m : (Lc - 1);
            cp16(sb + (uint32_t)(O_E + slot * ASTR + c * 4) * 4,
                 Er + (size_t)mc * HSc + c * 4);
        }
    };

    if (role == 1) {
        const float* qg = qkv + ((size_t)(b * Lc + i0)) * TDc + h * 64;
#pragma unroll
        for (int t = 0; t < 8; t++) {
            int idx = t128 + t * 128;
            int row = idx >> 4, c = idx & 15;
            cp16(sb + (uint32_t)(O_Q + row * ASTR + c * 4) * 4, qg + (size_t)row * TDc + c * 4);
        }
        load_kv(0, 0);
        load_e(mbase0, 128);
        cp_commit();
    }

    uint32_t aQh[8][4], aQl[8][4];
    float cO[8][4];      // S-warp: O1 ; R-warp: O2 (k-split partial)
    float m0 = -INFINITY, m1 = -INFINITY, l0 = 0.f, l1 = 0.f;
#pragma unroll
    for (int i = 0; i < 8; i++)
#pragma unroll
        for (int j = 0; j < 4; j++) cO[i][j] = 0.f;

    for (int kt = 0; kt <= qt; kt++) {
        const int mbase = mbase0 + kt * 64;
        cp_wait<0>();
        __syncthreads();       // B1: stage kt + E rows + (kt==0) Q visible

        if (kt == 0) {
#pragma unroll
            for (int ks = 0; ks < 8; ks++) {
                int base = (qr + g) * ASTR + 8 * ks + t4;
                float a0 = sf[O_Q + base];
                float a1 = sf[O_Q + base + 8 * ASTR];
                float a2 = sf[O_Q + base + 4];
                float a3 = sf[O_Q + base + 8 * ASTR + 4];
                float h0 = tf32_hi(a0), h1 = tf32_hi(a1), h2 = tf32_hi(a2), h3 = tf32_hi(a3);
                aQh[ks][0] = __float_as_uint(h0);
                aQh[ks][1] = __float_as_uint(h1);
                aQh[ks][2] = __float_as_uint(h2);
                aQh[ks][3] = __float_as_uint(h3);
                aQl[ks][0] = __float_as_uint(a0 - h0);
                aQl[ks][1] = __float_as_uint(a1 - h1);
                aQl[ks][2] = __float_as_uint(a2 - h2);
                aQl[ks][3] = __float_as_uint(a3 - h3);
            }
        }

        const int stg = kt & 1;
        const float* sK = sf + O_K + stg * 4352;
        const float* sV = sf + O_V + stg * 4352;

        float cS[8][4];
        if (role == 1) {
            // ---- R-gemm: only NEW band columns into rolling sSR ----
            const int nblk = (kt == 0) ? 16 : 8;
            const int mst  = (kt == 0) ? mbase : mbase + 63;
#pragma unroll 8
            for (int i = 0; i < nblk; i++) {
                const int mb = mst + i * 8;
                const int er = (mb + g) & 255;      // E ring row for this thread
                float acc[4] = {0.f, 0.f, 0.f, 0.f};
#pragma unroll
                for (int ks = 0; ks < 8; ks++) {
                    int eb = er * ASTR + 8 * ks + t4;
                    mma3(acc, aQh[ks], aQl[ks], sE[eb], sE[eb + 4]);
                }
                int c0 = mb + 2 * t4;
                int s0 = c0 & 127, s1 = (c0 + 1) & 127;
                sSR[(qr + g) * SRSTR + s0]     = acc[0];
                sSR[(qr + g) * SRSTR + s1]     = acc[1];
                sSR[(qr + g + 8) * SRSTR + s0] = acc[2];
                sSR[(qr + g + 8) * SRSTR + s1] = acc[3];
            }
        } else {
            // ---- S = Q K^T ----
#pragma unroll
            for (int nt = 0; nt < 8; nt++)
                cS[nt][0] = cS[nt][1] = cS[nt][2] = cS[nt][3] = 0.f;
#pragma unroll
            for (int ks = 0; ks < 8; ks++) {
#pragma unroll
                for (int nt = 0; nt < 8; nt++) {
                    int base = (nt * 8 + g) * ASTR + 8 * ks + t4;
                    mma3(cS[nt], aQh[ks], aQl[ks], sK[base], sK[base + 4]);
                }
            }
        }

        __syncthreads();       // B2: sR updated

        if (role == 0) {
            // ---- gather rel-pos + scale + causal mask (exp2 domain) ----
            const float scale2 = 0.18033688f;   // 0.125 * log2(e)
            const bool diag = (kt == qt);
            const int r0 = qr + g, r1 = qr + g + 8;
            const int gb0 = mbase + 63 - r0, gb1 = mbase + 63 - r1;
            float rm0 = -INFINITY, rm1 = -INFINITY;
#pragma unroll
            for (int nt = 0; nt < 8; nt++) {
                int jl = nt * 8 + 2 * t4;
                int ma = gb0 + jl, mb2 = gb1 + jl;
                float s0 = (cS[nt][0] + sSR[r0 * SRSTR + (ma & 127)]) * scale2;
                float s1 = (cS[nt][1] + sSR[r0 * SRSTR + ((ma + 1) & 127)]) * scale2;
                float s2 = (cS[nt][2] + sSR[r1 * SRSTR + (mb2 & 127)]) * scale2;
                float s3 = (cS[nt][3] + sSR[r1 * SRSTR + ((mb2 + 1) & 127)]) * scale2;
                if (diag) {
                    if (jl     > r0) s0 = -INFINITY;
                    if (jl + 1 > r0) s1 = -INFINITY;
                    if (jl     > r1) s2 = -INFINITY;
                    if (jl + 1 > r1) s3 = -INFINITY;
                }
                cS[nt][0] = s0; cS[nt][1] = s1; cS[nt][2] = s2; cS[nt][3] = s3;
                rm0 = fmaxf(rm0, fmaxf(s0, s1));
                rm1 = fmaxf(rm1, fmaxf(s2, s3));
            }
            rm0 = fmaxf(rm0, __shfl_xor_sync(0xFFFFFFFFu, rm0, 1));
            rm0 = fmaxf(rm0, __shfl_xor_sync(0xFFFFFFFFu, rm0, 2));
            rm1 = fmaxf(rm1, __shfl_xor_sync(0xFFFFFFFFu, rm1, 1));
            rm1 = fmaxf(rm1, __shfl_xor_sync(0xFFFFFFFFu, rm1, 2));
            float mn0 = fmaxf(m0, rm0), mn1 = fmaxf(m1, rm1);
            float al0 = ex2(m0 - mn0), al1 = ex2(m1 - mn1);

            float sum0 = 0.f, sum1 = 0.f;
#pragma unroll
            for (int nt = 0; nt < 8; nt++) {
                float p0 = ex2(cS[nt][0] - mn0);
                float p1 = ex2(cS[nt][1] - mn0);
                float p2 = ex2(cS[nt][2] - mn1);
                float p3 = ex2(cS[nt][3] - mn1);
                sum0 += p0 + p1; sum1 += p2 + p3;
                int col = nt * 8 + 2 * t4;
                *(float2*)&sP[r0 * ASTR + col] = make_float2(p0, p1);
                *(float2*)&sP[r1 * ASTR + col] = make_float2(p2, p3);
            }
            sum0 += __shfl_xor_sync(0xFFFFFFFFu, sum0, 1);
            sum0 += __shfl_xor_sync(0xFFFFFFFFu, sum0, 2);
            sum1 += __shfl_xor_sync(0xFFFFFFFFu, sum1, 1);
            sum1 += __shfl_xor_sync(0xFFFFFFFFu, sum1, 2);
            l0 = l0 * al0 + sum0;
            l1 = l1 * al1 + sum1;
            m0 = mn0; m1 = mn1;
            if (t4 == 0) {
                sAL[r0] = al0;
                sAL[r1] = al1;
            }
#pragma unroll
            for (int nt = 0; nt < 8; nt++) {
                cO[nt][0] *= al0; cO[nt][1] *= al0;
                cO[nt][2] *= al1; cO[nt][3] *= al1;
            }
        } else if (kt < qt) {
            // prefetch next stage K/V + 64 new Er ring rows
            load_kv(stg ^ 1, kt + 1);
            load_e(mbase + 128, 64);
            cp_commit();
        }

        __syncthreads();       // B3: P + alpha ready

        // ---- PV k-split: S-warp ks 0-3, R-warp ks 4-7 ----
        {
            float al0, al1;
            if (role == 1) {
                al0 = sAL[qr + g];
                al1 = sAL[qr + g + 8];
#pragma unroll
                for (int nt = 0; nt < 8; nt++) {
                    cO[nt][0] *= al0; cO[nt][1] *= al0;
                    cO[nt][2] *= al1; cO[nt][3] *= al1;
                }
            }
            const int ks0 = role ? 4 : 0;
#pragma unroll
            for (int kss = 0; kss < 4; kss++) {
                const int ks = ks0 + kss;
                int pb = (qr + g) * ASTR + 8 * ks + t4;
                float p0 = sP[pb];
                float p1 = sP[pb + 8 * ASTR];
                float p2 = sP[pb + 4];
                float p3 = sP[pb + 8 * ASTR + 4];
                float h0 = tf32_hi(p0), h1 = tf32_hi(p1), h2 = tf32_hi(p2), h3 = tf32_hi(p3);
                uint32_t ph[4] = { __float_as_uint(h0), __float_as_uint(h1),
                                   __float_as_uint(h2), __float_as_uint(h3) };
                uint32_t pl[4] = { __float_as_uint(p0 - h0), __float_as_uint(p1 - h1),
                                   __float_as_uint(p2 - h2), __float_as_uint(p3 - h3) };
#pragma unroll
                for (int nt = 0; nt < 8; nt++) {
                    float v0 = sV[(8 * ks + t4) * ASTR + nt * 8 + g];
                    float v1 = sV[(8 * ks + t4 + 4) * ASTR + nt * 8 + g];
                    mma3(cO[nt], ph, pl, v0, v1);
                }
            }
        }
    }

    // ---- epilogue: merge O2 into O1, normalize, store ----
    __syncthreads();
    if (role == 1) {
        const int r0 = qr + g, r1 = qr + g + 8;
#pragma unroll
        for (int nt = 0; nt < 8; nt++) {
            int col = nt * 8 + 2 * t4;
            *(float2*)&sP[r0 * ASTR + col] = make_float2(cO[nt][0], cO[nt][1]);
            *(float2*)&sP[r1 * ASTR + col] = make_float2(cO[nt][2], cO[nt][3]);
        }
    }
    __syncthreads();
    if (role == 0) {
        float inv0 = 1.f / l0, inv1 = 1.f / l1;
        const int r0 = qr + g, r1 = qr + g + 8;
        const int row0 = i0 + r0, row1 = i0 + r1;
#pragma unroll
        for (int nt = 0; nt < 8; nt++) {
            int d = nt * 8 + 2 * t4;
            float2 o2a = *(float2*)&sP[r0 * ASTR + d];
            float2 o2b = *(float2*)&sP[r1 * ASTR + d];
            float2 v0 = make_float2((cO[nt][0] + o2a.x) * inv0, (cO[nt][1] + o2a.y) * inv0);
            float2 v1 = make_float2((cO[nt][2] + o2b.x) * inv1, (cO[nt][3] + o2b.y) * inv1);
            *(float2*)&y[((size_t)(b * Lc + row0)) * Dc + h * 64 + d] = v0;
            *(float2*)&y[((size_t)(b * Lc + row1)) * Dc + h * 64 + d] = v1;
        }
    }
}

// ---------------------------------------------------------------------------
extern "C" void kernel_launch(void* const* d_in, const int* in_sizes, int n_in,
                              void* d_out, int out_size)
{
    const float* x     = (const float*)d_in[0];
    const float* Wqkv  = (const float*)d_in[1];
    const float* bqkv  = (const float*)d_in[2];
    const float* Wproj = (const float*)d_in[3];
    const float* bproj = (const float*)d_in[4];
    const float* Er    = (const float*)d_in[5];
    float* out = (float*)d_out;

    float *wqt, *wpt, *qkvp, *yp;
    cudaGetSymbolAddress((void**)&wqt, g_wqkvt);
    cudaGetSymbolAddress((void**)&wpt, g_wprojt);
    cudaGetSymbolAddress((void**)&qkvp, g_qkv);
    cudaGetSymbolAddress((void**)&yp, g_y);

    cudaFuncSetAttribute(gemm_tc,
                         cudaFuncAttributeMaxDynamicSharedMemorySize, (int)GSMEM);
    cudaFuncSetAttribute(attn_tc,
                         cudaFuncAttributeMaxDynamicSharedMemorySize, ATTN_SMEM);

    // transpose weights to [N,K]
    transpose_k<<<dim3(TDc / 32, Dc / 32), dim3(32, 8)>>>(Wqkv, wqt, Dc, TDc);
    transpose_k<<<dim3(Dc / 32, Dc / 32), dim3(32, 8)>>>(Wproj, wpt, Dc, Dc);

    // qkv = x @ Wqkv + bqkv
    gemm_tc<<<dim3(TDc / 128, Mrows / 128), 256, GSMEM>>>(
        x, wqt, bqkv, qkvp, Mrows, TDc, Dc);

    // tensor-core flash attention
    attn_tc<<<dim3(Lc / 64, Bc * NHc), 256, ATTN_SMEM>>>(qkvp, Er, yp);

    // out = y @ Wproj + bproj
    gemm_tc<<<dim3(Dc / 128, Mrows / 128), 256, GSMEM>>>(
        yp, wpt, bproj, out, Mrows, Dc, Dc);
}